// round 3
// baseline (speedup 1.0000x reference)
#include <cuda_runtime.h>
#include <math.h>

#define BB 8
#define SS 2048
#define DMODEL 512
#define HH 8
#define SDIM 64
#define NTOK (BB*SS)      /* 16384 */
#define HID 2048
#define NCH (BB*HH)       /* 64 */

typedef unsigned long long ull;

// ---------------- scratch (device globals: allocation-free rule) ----------------
__device__ float g_n   [NTOK*DMODEL];
__device__ float g_a   [NTOK*DMODEL];   // chain-major [B,H,S,64]
__device__ float g_bp  [NTOK*DMODEL];   // chain-major
__device__ float g_ql  [NTOK*DMODEL];   // chain-major
__device__ float g_qr  [NTOK*DMODEL];   // token-major [B,S,512]
__device__ float g_prev[NTOK*DMODEL];   // chain-major
__device__ float g_sd  [NCH*SS];
__device__ float g_pd  [NCH*SS];
__device__ float g_mix [NTOK*DMODEL];
__device__ float g_r   [NTOK*DMODEL];
__device__ float g_rn  [NTOK*DMODEL];
__device__ float g_h   [NTOK*HID];

// ---------------- f32x2 packed helpers (sm_103a) ----------------
__device__ __forceinline__ ull pk2(float a, float b) {
    ull r; asm("mov.b64 %0, {%1, %2};" : "=l"(r) : "f"(a), "f"(b)); return r;
}
__device__ __forceinline__ void upk2(ull v, float& a, float& b) {
    asm("mov.b64 {%0, %1}, %2;" : "=f"(a), "=f"(b) : "l"(v));
}
__device__ __forceinline__ ull fma2(ull a, ull b, ull c) {
    ull d; asm("fma.rn.f32x2 %0, %1, %2, %3;" : "=l"(d) : "l"(a), "l"(b), "l"(c)); return d;
}
__device__ __forceinline__ ull mul2(ull a, ull b) {
    ull d; asm("mul.rn.f32x2 %0, %1, %2;" : "=l"(d) : "l"(a), "l"(b)); return d;
}

// ---------------- LayerNorm ----------------
__global__ __launch_bounds__(256) void ln_kernel(
    const float* __restrict__ X, const float* __restrict__ G,
    const float* __restrict__ Bt, float* __restrict__ O)
{
    int row = blockIdx.x;
    int tid = threadIdx.x;
    const float* xr = X + (size_t)row*DMODEL;
    float2 v = *(const float2*)(xr + tid*2);
    float s  = v.x + v.y;
    float ss = v.x*v.x + v.y*v.y;
    #pragma unroll
    for (int m = 16; m > 0; m >>= 1) {
        s  += __shfl_xor_sync(0xffffffffu, s,  m);
        ss += __shfl_xor_sync(0xffffffffu, ss, m);
    }
    __shared__ float shs[8], shss[8];
    int w = tid >> 5, l = tid & 31;
    if (l == 0) { shs[w] = s; shss[w] = ss; }
    __syncthreads();
    if (tid == 0) {
        float S_ = 0.f, SS_ = 0.f;
        #pragma unroll
        for (int i = 0; i < 8; i++) { S_ += shs[i]; SS_ += shss[i]; }
        shs[0] = S_; shss[0] = SS_;
    }
    __syncthreads();
    float mean = shs[0] * (1.0f/DMODEL);
    float var  = shss[0] * (1.0f/DMODEL) - mean*mean;
    float inv  = rsqrtf(var + 1e-5f);
    float2 gv = *(const float2*)(G  + tid*2);
    float2 bv = *(const float2*)(Bt + tid*2);
    float2 o;
    o.x = (v.x - mean)*inv*gv.x + bv.x;
    o.y = (v.y - mean)*inv*gv.y + bv.y;
    *(float2*)(O + (size_t)row*DMODEL + tid*2) = o;
}

// ---------------- GEMM: C = act(A[M,K] @ W[N,K]^T + bias) (+resid), opt scatter ----------------
template<int ACT, bool SCAT, bool BIASF, bool RES>
__global__ __launch_bounds__(256) void gemm_kernel(
    const float* __restrict__ A, const float* __restrict__ W,
    const float* __restrict__ bias, const float* __restrict__ resid,
    float* __restrict__ C, int M, int N, int K)
{
    __shared__ __align__(16) float As[16][68];
    __shared__ __align__(16) float Ws[16][68];
    int tid = threadIdx.x;
    int tx = tid & 15, ty = tid >> 4;
    int m0 = blockIdx.y * 64, n0 = blockIdx.x * 64;
    int lr = tid >> 2, lc = (tid & 3) * 4;
    const float* Ag = A + (size_t)(m0 + lr)*K + lc;
    const float* Wg = W + (size_t)(n0 + lr)*K + lc;
    float acc[4][4];
    #pragma unroll
    for (int i = 0; i < 4; i++)
        #pragma unroll
        for (int j = 0; j < 4; j++) acc[i][j] = 0.f;

    for (int k0 = 0; k0 < K; k0 += 16) {
        float4 av = *(const float4*)(Ag + k0);
        float4 wv = *(const float4*)(Wg + k0);
        As[lc+0][lr] = av.x; As[lc+1][lr] = av.y; As[lc+2][lr] = av.z; As[lc+3][lr] = av.w;
        Ws[lc+0][lr] = wv.x; Ws[lc+1][lr] = wv.y; Ws[lc+2][lr] = wv.z; Ws[lc+3][lr] = wv.w;
        __syncthreads();
        #pragma unroll
        for (int k = 0; k < 16; k++) {
            float4 a = *(const float4*)&As[k][ty*4];
            float4 w = *(const float4*)&Ws[k][tx*4];
            float ar[4] = {a.x, a.y, a.z, a.w};
            float wr[4] = {w.x, w.y, w.z, w.w};
            #pragma unroll
            for (int i = 0; i < 4; i++)
                #pragma unroll
                for (int j = 0; j < 4; j++) acc[i][j] += ar[i]*wr[j];
        }
        __syncthreads();
    }
    #pragma unroll
    for (int i = 0; i < 4; i++) {
        int row = m0 + ty*4 + i;
        #pragma unroll
        for (int j = 0; j < 4; j++) {
            int col = n0 + tx*4 + j;
            float v = acc[i][j];
            if (BIASF) v += __ldg(bias + col);
            if (ACT == 1) v = tanhf(v);
            if (ACT == 2) v = 0.5f * v * (1.0f + erff(v * 0.70710678118654752f));
            if (RES)   v += __ldg(resid + (size_t)row*N + col);
            size_t idx;
            if (SCAT) {
                // token (row=b*S+t), col=h*64+d -> chain-major [(b*8+h)*S + t]*64 + d
                idx = ((size_t)((row >> 11)*HH + (col >> 6)))*((size_t)SS*64)
                    + (size_t)(row & (SS-1))*64 + (size_t)(col & 63);
            } else {
                idx = (size_t)row*N + col;
            }
            C[idx] = v;
        }
    }
}

// ---------------- sd/pd gates: sigmoid(n . Wsd[h] + bsd[h]) ----------------
__global__ __launch_bounds__(256) void sdpd_kernel(
    const float* __restrict__ Nn, const float* __restrict__ Wsd, const float* __restrict__ bsd,
    const float* __restrict__ Wpd, const float* __restrict__ bpd,
    float* __restrict__ sd_o, float* __restrict__ pd_o)
{
    __shared__ float Wsh[16][512];
    __shared__ float nsh[512];
    int tid = threadIdx.x;
    #pragma unroll
    for (int k = 0; k < 32; k++) {
        int idx = tid + 256*k;             // 0..8191
        float v = (idx < 4096) ? Wsd[idx] : Wpd[idx - 4096];
        Wsh[idx >> 9][idx & 511] = v;
    }
    int o = tid >> 4, p = tid & 15;
    float bias_v = (o < 8) ? __ldg(bsd + o) : __ldg(bpd + o - 8);
    for (int tk = 0; tk < 8; tk++) {
        int token = blockIdx.x*8 + tk;
        __syncthreads();
        nsh[tid]       = Nn[(size_t)token*512 + tid];
        nsh[tid + 256] = Nn[(size_t)token*512 + tid + 256];
        __syncthreads();
        float s = 0.f;
        #pragma unroll
        for (int i = 0; i < 32; i++) {
            int d = i*16 + p;
            s += nsh[d] * Wsh[o][d];
        }
        s += __shfl_xor_sync(0xffffffffu, s, 8);
        s += __shfl_xor_sync(0xffffffffu, s, 4);
        s += __shfl_xor_sync(0xffffffffu, s, 2);
        s += __shfl_xor_sync(0xffffffffu, s, 1);
        if (p == 0) {
            float z = s + bias_v;
            float sg = 1.0f / (1.0f + expf(-z));
            int b = token >> 11, t = token & (SS-1);
            int h = o & 7;
            size_t oi = ((size_t)(b*8 + h))*SS + t;
            if (o < 8) sd_o[oi] = sg; else pd_o[oi] = sg;
        }
    }
}

// ---------------- state scan: prev[t] = state_{t-1}; state = sd*state + (1-sd)*a ----------------
__global__ __launch_bounds__(64) void state_scan_kernel(
    const float* __restrict__ a, const float* __restrict__ sd, float* __restrict__ prev)
{
    int chain = blockIdx.x, tid = threadIdx.x;
    const float* aP  = a  + (size_t)chain*SS*64;
    const float* sdP = sd + (size_t)chain*SS;
    float* pP        = prev + (size_t)chain*SS*64;
    float st = 0.0f;
    for (int t0 = 0; t0 < SS; t0 += 8) {
        float av[8], sv[8];
        #pragma unroll
        for (int j = 0; j < 8; j++) av[j] = aP[(size_t)(t0+j)*64 + tid];
        #pragma unroll
        for (int j = 0; j < 8; j++) sv[j] = __ldg(sdP + t0 + j);
        #pragma unroll
        for (int j = 0; j < 8; j++) {
            pP[(size_t)(t0+j)*64 + tid] = st;
            st = sv[j]*st + (1.0f - sv[j])*av[j];
        }
    }
}

// ---------------- pair scan: the serial core ----------------
// Thread layout: e = tid>>2 (pair column), q = tid&3 (quarter of d-range).
// Each thread holds pair[d][e] for d in [16q,16q+16) as 8 packed f32x2 registers.
// pair = pd*pair + (1-pd)*outer(prev,b);  lc[e] = sum_d pair[d][e]*ql[d]
__global__ __launch_bounds__(256) void pair_scan_kernel(
    const float* __restrict__ prevA, const float* __restrict__ bA,
    const float* __restrict__ qlA,   const float* __restrict__ pdA,
    const float* __restrict__ qrA,   float* __restrict__ mixA)
{
    int chain = blockIdx.x;
    int bb = chain >> 3, hh = chain & 7;
    const float* prevC = prevA + (size_t)chain*SS*64;
    const float* bC    = bA    + (size_t)chain*SS*64;
    const float* qlC   = qlA   + (size_t)chain*SS*64;
    const float* pdC   = pdA   + (size_t)chain*SS;

    __shared__ __align__(16) float sh[2][6][64]; // [phase][prev_t,b_t,ql_t,prev_t1,b_t1,ql_t1][d]
    int tid = threadIdx.x;
    int e = tid >> 2, q = tid & 3;
    int seg0 = tid >> 6, off0 = tid & 63;

    ull col2[8];
    #pragma unroll
    for (int i = 0; i < 8; i++) col2[i] = 0ULL;

    auto do_load = [&](int t, int ph) {
        size_t o = (size_t)t * 64;
        const float* s0;
        if      (seg0 == 0) s0 = prevC + o;
        else if (seg0 == 1) s0 = bC + o;
        else if (seg0 == 2) s0 = qlC + o;
        else                s0 = prevC + o + 64;
        sh[ph][seg0][off0] = s0[off0];
        if (tid < 128) {
            int seg1 = 4 + (tid >> 6);
            const float* s1 = (seg1 == 4) ? (bC + o + 64) : (qlC + o + 64);
            sh[ph][seg1][off0] = s1[off0];
        }
    };

    do_load(0, 0);
    __syncthreads();

    for (int t = 0; t < SS; t += 2) {
        int ph = (t >> 1) & 1;
        if (t + 2 < SS) do_load(t + 2, ph ^ 1);
        float2 pdv = *(const float2*)(pdC + t);
        #pragma unroll
        for (int sub = 0; sub < 2; sub++) {
            float pd = sub ? pdv.y : pdv.x;
            float w  = (1.0f - pd) * sh[ph][1 + sub*3][e];
            ull pd2 = pk2(pd, pd);
            ull w2  = pk2(w, w);
            ull dot2 = 0ULL;
            const float* pv = &sh[ph][0 + sub*3][q*16];
            const float* qv = &sh[ph][2 + sub*3][q*16];
            #pragma unroll
            for (int i = 0; i < 8; i++) {
                ull p2 = *(const ull*)(pv + 2*i);
                ull q2 = *(const ull*)(qv + 2*i);
                col2[i] = fma2(col2[i], pd2, mul2(w2, p2));   // pair = pd*pair + (1-pd)*b[e]*prev[d]
                dot2    = fma2(col2[i], q2, dot2);            // lc partial
            }
            float dl, dh;
            upk2(dot2, dl, dh);
            float dot = dl + dh;
            dot += __shfl_xor_sync(0xffffffffu, dot, 1);
            dot += __shfl_xor_sync(0xffffffffu, dot, 2);
            if (q == 0) {
                size_t oo = ((size_t)bb*SS + (size_t)(t + sub))*DMODEL + hh*64 + e;
                mixA[oo] = dot * __ldg(qrA + oo);
            }
        }
        __syncthreads();
    }
}

// ---------------- host ----------------
extern "C" void kernel_launch(void* const* d_in, const int* in_sizes, int n_in,
                              void* d_out, int out_size)
{
    const float* x    = (const float*)d_in[0];
    const float* ng   = (const float*)d_in[1];
    const float* nb   = (const float*)d_in[2];
    const float* fg   = (const float*)d_in[3];
    const float* fb   = (const float*)d_in[4];
    const float* Wa   = (const float*)d_in[5];
    const float* Wb   = (const float*)d_in[6];
    const float* Wql  = (const float*)d_in[7];
    const float* Wqr  = (const float*)d_in[8];
    const float* Wsd  = (const float*)d_in[9];
    const float* bsd  = (const float*)d_in[10];
    const float* Wpd  = (const float*)d_in[11];
    const float* bpd  = (const float*)d_in[12];
    const float* Wout = (const float*)d_in[13];
    const float* W1   = (const float*)d_in[14];
    const float* b1   = (const float*)d_in[15];
    const float* W2   = (const float*)d_in[16];
    const float* b2   = (const float*)d_in[17];
    float* out = (float*)d_out;

    float *n_, *a_, *b_, *ql_, *qr_, *prev_, *sd_, *pd_, *mix_, *r_, *rn_, *h_;
    cudaGetSymbolAddress((void**)&n_,    g_n);
    cudaGetSymbolAddress((void**)&a_,    g_a);
    cudaGetSymbolAddress((void**)&b_,    g_bp);
    cudaGetSymbolAddress((void**)&ql_,   g_ql);
    cudaGetSymbolAddress((void**)&qr_,   g_qr);
    cudaGetSymbolAddress((void**)&prev_, g_prev);
    cudaGetSymbolAddress((void**)&sd_,   g_sd);
    cudaGetSymbolAddress((void**)&pd_,   g_pd);
    cudaGetSymbolAddress((void**)&mix_,  g_mix);
    cudaGetSymbolAddress((void**)&r_,    g_r);
    cudaGetSymbolAddress((void**)&rn_,   g_rn);
    cudaGetSymbolAddress((void**)&h_,    g_h);

    // 1) LN(x)
    ln_kernel<<<NTOK, 256>>>(x, ng, nb, n_);

    // 2) projections
    dim3 g512(512/64, NTOK/64);
    gemm_kernel<1, true,  false, false><<<g512, 256>>>(n_, Wa,  nullptr, nullptr, a_,  NTOK, 512, 512);
    gemm_kernel<1, true,  false, false><<<g512, 256>>>(n_, Wb,  nullptr, nullptr, b_,  NTOK, 512, 512);
    gemm_kernel<1, true,  false, false><<<g512, 256>>>(n_, Wql, nullptr, nullptr, ql_, NTOK, 512, 512);
    gemm_kernel<1, false, false, false><<<g512, 256>>>(n_, Wqr, nullptr, nullptr, qr_, NTOK, 512, 512);
    sdpd_kernel<<<NTOK/8, 256>>>(n_, Wsd, bsd, Wpd, bpd, sd_, pd_);

    // 3) scans
    state_scan_kernel<<<NCH, 64>>>(a_, sd_, prev_);
    pair_scan_kernel<<<NCH, 256>>>(prev_, b_, ql_, pd_, qr_, mix_);

    // 4) r = x + mix @ Wout^T
    gemm_kernel<0, false, false, true><<<g512, 256>>>(mix_, Wout, nullptr, x, r_, NTOK, 512, 512);

    // 5) FFN
    ln_kernel<<<NTOK, 256>>>(r_, fg, fb, rn_);
    dim3 gW1(HID/64, NTOK/64);
    gemm_kernel<2, false, true, false><<<gW1, 256>>>(rn_, W1, b1, nullptr, h_, NTOK, HID, 512);
    dim3 gW2(512/64, NTOK/64);
    gemm_kernel<0, false, true, true><<<gW2, 256>>>(h_, W2, b2, r_, out, NTOK, 512, HID);
}

// round 4
// speedup vs baseline: 1.2444x; 1.2444x over previous
#include <cuda_runtime.h>
#include <math.h>

#define BB 8
#define SS 2048
#define DMODEL 512
#define HH 8
#define NTOK (BB*SS)      /* 16384 */
#define HID 2048
#define NCH (BB*HH)       /* 64 */
#define NCHUNK 32         /* 2048/64 */

typedef unsigned long long ull;

// ---------------- scratch (device globals: allocation-free rule) ----------------
__device__ float g_n   [NTOK*DMODEL];
__device__ float g_a   [NTOK*DMODEL];   // chain-major [B,H,S,64]
__device__ float g_bp  [NTOK*DMODEL];   // chain-major
__device__ float g_ql  [NTOK*DMODEL];   // chain-major
__device__ float g_qr  [NTOK*DMODEL];   // token-major [B,S,512]
__device__ float g_prev[NTOK*DMODEL];   // chain-major
__device__ float g_sd  [NCH*SS];
__device__ float g_pd  [NCH*SS];
__device__ float g_mix [NTOK*DMODEL];
__device__ float g_r   [NTOK*DMODEL];
__device__ float g_rn  [NTOK*DMODEL];
__device__ float g_h   [NTOK*HID];
__device__ float g_P   [(size_t)NCH*NCHUNK*64*64];  // P snapshot at each chunk start

// ---------------- f32x2 packed helpers (sm_103a) ----------------
__device__ __forceinline__ ull pk2(float a, float b) {
    ull r; asm("mov.b64 %0, {%1, %2};" : "=l"(r) : "f"(a), "f"(b)); return r;
}
__device__ __forceinline__ void upk2(ull v, float& a, float& b) {
    asm("mov.b64 {%0, %1}, %2;" : "=f"(a), "=f"(b) : "l"(v));
}
__device__ __forceinline__ ull fma2(ull a, ull b, ull c) {
    ull d; asm("fma.rn.f32x2 %0, %1, %2, %3;" : "=l"(d) : "l"(a), "l"(b), "l"(c)); return d;
}
__device__ __forceinline__ ull mul2(ull a, ull b) {
    ull d; asm("mul.rn.f32x2 %0, %1, %2;" : "=l"(d) : "l"(a), "l"(b)); return d;
}

// ---------------- LayerNorm ----------------
__global__ __launch_bounds__(256) void ln_kernel(
    const float* __restrict__ X, const float* __restrict__ G,
    const float* __restrict__ Bt, float* __restrict__ O)
{
    int row = blockIdx.x;
    int tid = threadIdx.x;
    const float* xr = X + (size_t)row*DMODEL;
    float2 v = *(const float2*)(xr + tid*2);
    float s  = v.x + v.y;
    float ss = v.x*v.x + v.y*v.y;
    #pragma unroll
    for (int m = 16; m > 0; m >>= 1) {
        s  += __shfl_xor_sync(0xffffffffu, s,  m);
        ss += __shfl_xor_sync(0xffffffffu, ss, m);
    }
    __shared__ float shs[8], shss[8];
    int w = tid >> 5, l = tid & 31;
    if (l == 0) { shs[w] = s; shss[w] = ss; }
    __syncthreads();
    if (tid == 0) {
        float S_ = 0.f, SS_ = 0.f;
        #pragma unroll
        for (int i = 0; i < 8; i++) { S_ += shs[i]; SS_ += shss[i]; }
        shs[0] = S_; shss[0] = SS_;
    }
    __syncthreads();
    float mean = shs[0] * (1.0f/DMODEL);
    float var  = shss[0] * (1.0f/DMODEL) - mean*mean;
    float inv  = rsqrtf(var + 1e-5f);
    float2 gv = *(const float2*)(G  + tid*2);
    float2 bv = *(const float2*)(Bt + tid*2);
    float2 o;
    o.x = (v.x - mean)*inv*gv.x + bv.x;
    o.y = (v.y - mean)*inv*gv.y + bv.y;
    *(float2*)(O + (size_t)row*DMODEL + tid*2) = o;
}

// ---------------- GEMM: C = act(A[M,K] @ W[N,K]^T + bias) (+resid), opt scatter ----
// 128x64 tile, 256 threads, 8x4 micro-tile, f32x2 packed along K (even/odd partials).
template<int ACT, bool SCAT, bool BIASF, bool RES>
__global__ __launch_bounds__(256, 2) void gemm_kernel(
    const float* __restrict__ A, const float* __restrict__ W,
    const float* __restrict__ bias, const float* __restrict__ resid,
    float* __restrict__ C, int M, int N, int K)
{
    __shared__ float As[128*18];  // [m][k], k-minor, pad 18
    __shared__ float Ws[64*18];   // [n][k]
    int tid = threadIdx.x;
    int m0 = blockIdx.y * 128, n0 = blockIdx.x * 64;
    int alr = tid >> 1, akc = (tid & 1) * 8;
    int wlr = tid >> 2, wkc = (tid & 3) * 4;
    const float* Ag = A + (size_t)(m0 + alr)*K + akc;
    const float* Wg = W + (size_t)(n0 + wlr)*K + wkc;
    int ty = tid >> 4, tx = tid & 15;
    int mB = ty * 8, nB = tx * 4;

    ull acc2[8][4];
    #pragma unroll
    for (int i = 0; i < 8; i++)
        #pragma unroll
        for (int j = 0; j < 4; j++) acc2[i][j] = 0ULL;

    float4 a0 = *(const float4*)(Ag);
    float4 a1 = *(const float4*)(Ag + 4);
    float4 w0 = *(const float4*)(Wg);

    for (int k0 = 0; k0 < K; k0 += 16) {
        __syncthreads();
        *(float2*)&As[alr*18 + akc    ] = make_float2(a0.x, a0.y);
        *(float2*)&As[alr*18 + akc + 2] = make_float2(a0.z, a0.w);
        *(float2*)&As[alr*18 + akc + 4] = make_float2(a1.x, a1.y);
        *(float2*)&As[alr*18 + akc + 6] = make_float2(a1.z, a1.w);
        *(float2*)&Ws[wlr*18 + wkc    ] = make_float2(w0.x, w0.y);
        *(float2*)&Ws[wlr*18 + wkc + 2] = make_float2(w0.z, w0.w);
        __syncthreads();
        if (k0 + 16 < K) {
            a0 = *(const float4*)(Ag + k0 + 16);
            a1 = *(const float4*)(Ag + k0 + 20);
            w0 = *(const float4*)(Wg + k0 + 16);
        }
        #pragma unroll
        for (int kp = 0; kp < 8; kp++) {
            ull ap[8], wp[4];
            #pragma unroll
            for (int i = 0; i < 8; i++) ap[i] = *(const ull*)&As[(mB+i)*18 + 2*kp];
            #pragma unroll
            for (int j = 0; j < 4; j++) wp[j] = *(const ull*)&Ws[(nB+j)*18 + 2*kp];
            #pragma unroll
            for (int i = 0; i < 8; i++)
                #pragma unroll
                for (int j = 0; j < 4; j++)
                    acc2[i][j] = fma2(ap[i], wp[j], acc2[i][j]);
        }
    }

    #pragma unroll
    for (int i = 0; i < 8; i++) {
        int row = m0 + mB + i;
        #pragma unroll
        for (int j = 0; j < 4; j++) {
            int col = n0 + nB + j;
            float lo, hi; upk2(acc2[i][j], lo, hi);
            float v = lo + hi;
            if (BIASF) v += __ldg(bias + col);
            if (ACT == 1) v = tanhf(v);
            if (ACT == 2) v = 0.5f * v * (1.0f + erff(v * 0.70710678118654752f));
            if (RES)   v += __ldg(resid + (size_t)row*N + col);
            size_t idx;
            if (SCAT) {
                idx = ((size_t)((row >> 11)*HH + (col >> 6)))*((size_t)SS*64)
                    + (size_t)(row & (SS-1))*64 + (size_t)(col & 63);
            } else {
                idx = (size_t)row*N + col;
            }
            C[idx] = v;
        }
    }
}

// ---------------- sd/pd gates ----------------
__global__ __launch_bounds__(256) void sdpd_kernel(
    const float* __restrict__ Nn, const float* __restrict__ Wsd, const float* __restrict__ bsd,
    const float* __restrict__ Wpd, const float* __restrict__ bpd,
    float* __restrict__ sd_o, float* __restrict__ pd_o)
{
    __shared__ float Wsh[16][512];
    __shared__ float nsh[512];
    int tid = threadIdx.x;
    #pragma unroll
    for (int k = 0; k < 32; k++) {
        int idx = tid + 256*k;
        float v = (idx < 4096) ? Wsd[idx] : Wpd[idx - 4096];
        Wsh[idx >> 9][idx & 511] = v;
    }
    int o = tid >> 4, p = tid & 15;
    float bias_v = (o < 8) ? __ldg(bsd + o) : __ldg(bpd + o - 8);
    for (int tk = 0; tk < 8; tk++) {
        int token = blockIdx.x*8 + tk;
        __syncthreads();
        nsh[tid]       = Nn[(size_t)token*512 + tid];
        nsh[tid + 256] = Nn[(size_t)token*512 + tid + 256];
        __syncthreads();
        float s = 0.f;
        #pragma unroll
        for (int i = 0; i < 32; i++) {
            int d = i*16 + p;
            s += nsh[d] * Wsh[o][d];
        }
        s += __shfl_xor_sync(0xffffffffu, s, 8);
        s += __shfl_xor_sync(0xffffffffu, s, 4);
        s += __shfl_xor_sync(0xffffffffu, s, 2);
        s += __shfl_xor_sync(0xffffffffu, s, 1);
        if (p == 0) {
            float z = s + bias_v;
            float sg = 1.0f / (1.0f + expf(-z));
            int b = token >> 11, t = token & (SS-1);
            int h = o & 7;
            size_t oi = ((size_t)(b*8 + h))*SS + t;
            if (o < 8) sd_o[oi] = sg; else pd_o[oi] = sg;
        }
    }
}

// ---------------- state scan: prev[t] = state_{t-1} ----------------
__global__ __launch_bounds__(64) void state_scan_kernel(
    const float* __restrict__ a, const float* __restrict__ sd, float* __restrict__ prev)
{
    int chain = blockIdx.x, tid = threadIdx.x;
    const float* aP  = a  + (size_t)chain*SS*64;
    const float* sdP = sd + (size_t)chain*SS;
    float* pP        = prev + (size_t)chain*SS*64;
    float st = 0.0f;
    for (int t0 = 0; t0 < SS; t0 += 8) {
        float av[8], sv[8];
        #pragma unroll
        for (int j = 0; j < 8; j++) av[j] = aP[(size_t)(t0+j)*64 + tid];
        #pragma unroll
        for (int j = 0; j < 8; j++) sv[j] = __ldg(sdP + t0 + j);
        #pragma unroll
        for (int j = 0; j < 8; j++) {
            pP[(size_t)(t0+j)*64 + tid] = st;
            st = sv[j]*st + (1.0f - sv[j])*av[j];
        }
    }
}

// ---------------- chunked pair recurrence, phase 1: P snapshots ----------------
// P' = cp63*P + sum_j u_j * prev_j b_j^T,  u_j = (1-pd_j)*cp63/cp_j
// One block per chain; P held in registers (thread owns 4x4 tile).
__global__ __launch_bounds__(256) void pair_phase1_kernel(
    const float* __restrict__ prevA, const float* __restrict__ bA,
    const float* __restrict__ pdA, float* __restrict__ Psnap)
{
    int chain = blockIdx.x;
    const float* prevC = prevA + (size_t)chain*SS*64;
    const float* bC    = bA    + (size_t)chain*SS*64;
    const float* pdC   = pdA   + (size_t)chain*SS;
    __shared__ float prev_s[64*66];
    __shared__ float b_s[64*66];
    __shared__ float sh_pd[64], sh_cp[64], sh_u[64];
    int tid = threadIdx.x;
    int d0 = (tid >> 4) * 4, e0 = (tid & 15) * 4;
    int r = tid >> 2, cc = (tid & 3) * 16;

    ull p2[4][2];
    #pragma unroll
    for (int i = 0; i < 4; i++) { p2[i][0] = 0ULL; p2[i][1] = 0ULL; }

    for (int c = 0; c < NCHUNK; c++) {
        __syncthreads();
        {
            const float* gp = prevC + ((size_t)c*64 + r)*64 + cc;
            const float* gb = bC    + ((size_t)c*64 + r)*64 + cc;
            #pragma unroll
            for (int q = 0; q < 4; q++) {
                float4 v = *(const float4*)(gp + q*4);
                *(float2*)&prev_s[r*66 + cc + q*4    ] = make_float2(v.x, v.y);
                *(float2*)&prev_s[r*66 + cc + q*4 + 2] = make_float2(v.z, v.w);
                float4 u = *(const float4*)(gb + q*4);
                *(float2*)&b_s[r*66 + cc + q*4    ] = make_float2(u.x, u.y);
                *(float2*)&b_s[r*66 + cc + q*4 + 2] = make_float2(u.z, u.w);
            }
            if (tid < 64) sh_pd[tid] = pdC[c*64 + tid];
        }
        __syncthreads();
        if (tid == 0) {
            float cp = 1.0f;
            for (int j = 0; j < 64; j++) { cp = fmaxf(cp * sh_pd[j], 1e-35f); sh_cp[j] = cp; }
        }
        __syncthreads();
        if (tid < 64) sh_u[tid] = (1.0f - sh_pd[tid]) * (sh_cp[63] / sh_cp[tid]);
        // snapshot P (state at chunk start)
        float* Pc = Psnap + (((size_t)chain*NCHUNK + c)*64)*64;
        #pragma unroll
        for (int i = 0; i < 4; i++) {
            float l0, h0, l1, h1;
            upk2(p2[i][0], l0, h0); upk2(p2[i][1], l1, h1);
            float4 v = make_float4(l0, h0, l1, h1);
            *(float4*)(Pc + (size_t)(d0+i)*64 + e0) = v;
        }
        __syncthreads();
        float cpE = sh_cp[63];
        ull cpE2 = pk2(cpE, cpE);
        #pragma unroll
        for (int i = 0; i < 4; i++) {
            p2[i][0] = mul2(p2[i][0], cpE2);
            p2[i][1] = mul2(p2[i][1], cpE2);
        }
        for (int j = 0; j < 64; j++) {
            float uj = sh_u[j];
            ull b20 = *(const ull*)&b_s[j*66 + e0];
            ull b21 = *(const ull*)&b_s[j*66 + e0 + 2];
            #pragma unroll
            for (int i = 0; i < 4; i++) {
                float s = uj * prev_s[j*66 + d0 + i];
                ull s2 = pk2(s, s);
                p2[i][0] = fma2(s2, b20, p2[i][0]);
                p2[i][1] = fma2(s2, b21, p2[i][1]);
            }
        }
    }
}

// ---------------- chunked pair, phase 2: per-(chain,chunk) mini-GEMMs ----------------
// G[t][j] = ql_t . prev_j ; W = G * mask(j<=t)*(1-pd_j)*cp_t/cp_j
// lc[t] = W @ b + cp_t * (ql_t @ P); mix = lc * qr
__global__ __launch_bounds__(256) void pair_phase2_kernel(
    const float* __restrict__ prevA, const float* __restrict__ bA,
    const float* __restrict__ qlA,   const float* __restrict__ pdA,
    const float* __restrict__ qrA,   const float* __restrict__ Psnap,
    float* __restrict__ mixA)
{
    int blk = blockIdx.x;
    int chain = blk >> 5, c = blk & 31;
    int bb = chain >> 3, hh = chain & 7;
    const float* prevC = prevA + (size_t)chain*SS*64;
    const float* bC    = bA    + (size_t)chain*SS*64;
    const float* qlC   = qlA   + (size_t)chain*SS*64;
    const float* pdC   = pdA   + (size_t)chain*SS;
    const float* Pc    = Psnap + (((size_t)chain*NCHUNK + c)*64)*64;

    extern __shared__ float sm[];
    float* ql_s = sm;              // [64][66]
    float* pw_s = sm + 4224;       // prev, then overwritten with W
    float* b_s  = sm + 8448;
    float* P_s  = sm + 12672;
    float* sh_pd  = sm + 16896;
    float* sh_cp  = sh_pd + 64;
    float* sh_inv = sh_cp + 64;

    int tid = threadIdx.x;
    int r = tid >> 2, cc = (tid & 3) * 16;
    {
        const float* gq = qlC   + ((size_t)c*64 + r)*64 + cc;
        const float* gp = prevC + ((size_t)c*64 + r)*64 + cc;
        const float* gb = bC    + ((size_t)c*64 + r)*64 + cc;
        const float* gP = Pc    + (size_t)r*64 + cc;
        #pragma unroll
        for (int q = 0; q < 4; q++) {
            float4 v;
            v = *(const float4*)(gq + q*4);
            *(float2*)&ql_s[r*66 + cc + q*4    ] = make_float2(v.x, v.y);
            *(float2*)&ql_s[r*66 + cc + q*4 + 2] = make_float2(v.z, v.w);
            v = *(const float4*)(gp + q*4);
            *(float2*)&pw_s[r*66 + cc + q*4    ] = make_float2(v.x, v.y);
            *(float2*)&pw_s[r*66 + cc + q*4 + 2] = make_float2(v.z, v.w);
            v = *(const float4*)(gb + q*4);
            *(float2*)&b_s[r*66 + cc + q*4    ] = make_float2(v.x, v.y);
            *(float2*)&b_s[r*66 + cc + q*4 + 2] = make_float2(v.z, v.w);
            v = *(const float4*)(gP + q*4);
            *(float2*)&P_s[r*66 + cc + q*4    ] = make_float2(v.x, v.y);
            *(float2*)&P_s[r*66 + cc + q*4 + 2] = make_float2(v.z, v.w);
        }
        if (tid < 64) sh_pd[tid] = pdC[c*64 + tid];
    }
    __syncthreads();
    if (tid == 0) {
        float cp = 1.0f;
        for (int j = 0; j < 64; j++) { cp = fmaxf(cp * sh_pd[j], 1e-35f); sh_cp[j] = cp; }
    }
    __syncthreads();
    if (tid < 64) sh_inv[tid] = 1.0f / sh_cp[tid];

    int t0 = (tid >> 4) * 4, j0 = (tid & 15) * 4;
    // ---- G = ql @ prev^T (packed over d) ----
    ull g2[4][4];
    #pragma unroll
    for (int i = 0; i < 4; i++)
        #pragma unroll
        for (int j = 0; j < 4; j++) g2[i][j] = 0ULL;
    #pragma unroll 8
    for (int kp = 0; kp < 32; kp++) {
        ull aq[4], pj[4];
        #pragma unroll
        for (int i = 0; i < 4; i++) aq[i] = *(const ull*)&ql_s[(t0+i)*66 + 2*kp];
        #pragma unroll
        for (int j = 0; j < 4; j++) pj[j] = *(const ull*)&pw_s[(j0+j)*66 + 2*kp];
        #pragma unroll
        for (int i = 0; i < 4; i++)
            #pragma unroll
            for (int j = 0; j < 4; j++)
                g2[i][j] = fma2(aq[i], pj[j], g2[i][j]);
    }
    float wv[4][4];
    #pragma unroll
    for (int i = 0; i < 4; i++) {
        int tt = t0 + i;
        float cpt = sh_cp[tt];
        #pragma unroll
        for (int j = 0; j < 4; j++) {
            int jj = j0 + j;
            float lo, hi; upk2(g2[i][j], lo, hi);
            float coef = (jj <= tt) ? (1.0f - sh_pd[jj]) * cpt * sh_inv[jj] : 0.0f;
            wv[i][j] = (lo + hi) * coef;
        }
    }
    __syncthreads();   // all reads of pw_s (prev) done
    #pragma unroll
    for (int i = 0; i < 4; i++)
        #pragma unroll
        for (int j = 0; j < 4; j++)
            pw_s[(t0+i)*66 + (j0+j)] = wv[i][j];
    __syncthreads();

    // ---- lc = W @ b + cp_t * (ql @ P) ----
    int e0 = j0;  // reuse 4-wide e-group
    ull lc2[4][2], st2[4][2];
    #pragma unroll
    for (int i = 0; i < 4; i++) { lc2[i][0]=lc2[i][1]=st2[i][0]=st2[i][1]=0ULL; }
    for (int j = 0; j < 64; j++) {
        ull b20 = *(const ull*)&b_s[j*66 + e0];
        ull b21 = *(const ull*)&b_s[j*66 + e0 + 2];
        ull P20 = *(const ull*)&P_s[j*66 + e0];
        ull P21 = *(const ull*)&P_s[j*66 + e0 + 2];
        #pragma unroll
        for (int i = 0; i < 4; i++) {
            float w = pw_s[(t0+i)*66 + j];
            ull w2 = pk2(w, w);
            lc2[i][0] = fma2(w2, b20, lc2[i][0]);
            lc2[i][1] = fma2(w2, b21, lc2[i][1]);
            float q = ql_s[(t0+i)*66 + j];
            ull q2 = pk2(q, q);
            st2[i][0] = fma2(q2, P20, st2[i][0]);
            st2[i][1] = fma2(q2, P21, st2[i][1]);
        }
    }
    #pragma unroll
    for (int i = 0; i < 4; i++) {
        float cpt = sh_cp[t0 + i];
        ull cp2 = pk2(cpt, cpt);
        ull r0 = fma2(cp2, st2[i][0], lc2[i][0]);
        ull r1 = fma2(cp2, st2[i][1], lc2[i][1]);
        float l0, h0, l1, h1;
        upk2(r0, l0, h0); upk2(r1, l1, h1);
        int tglob = c*64 + t0 + i;
        size_t oo = ((size_t)bb*SS + tglob)*DMODEL + (size_t)hh*64 + e0;
        float4 qr4 = *(const float4*)(qrA + oo);
        float4 ov = make_float4(l0*qr4.x, h0*qr4.y, l1*qr4.z, h1*qr4.w);
        *(float4*)(mixA + oo) = ov;
    }
}

// ---------------- host ----------------
extern "C" void kernel_launch(void* const* d_in, const int* in_sizes, int n_in,
                              void* d_out, int out_size)
{
    const float* x    = (const float*)d_in[0];
    const float* ng   = (const float*)d_in[1];
    const float* nb   = (const float*)d_in[2];
    const float* fg   = (const float*)d_in[3];
    const float* fb   = (const float*)d_in[4];
    const float* Wa   = (const float*)d_in[5];
    const float* Wb   = (const float*)d_in[6];
    const float* Wql  = (const float*)d_in[7];
    const float* Wqr  = (const float*)d_in[8];
    const float* Wsd  = (const float*)d_in[9];
    const float* bsd  = (const float*)d_in[10];
    const float* Wpd  = (const float*)d_in[11];
    const float* bpd  = (const float*)d_in[12];
    const float* Wout = (const float*)d_in[13];
    const float* W1   = (const float*)d_in[14];
    const float* b1   = (const float*)d_in[15];
    const float* W2   = (const float*)d_in[16];
    const float* b2   = (const float*)d_in[17];
    float* out = (float*)d_out;

    float *n_, *a_, *b_, *ql_, *qr_, *prev_, *sd_, *pd_, *mix_, *r_, *rn_, *h_, *P_;
    cudaGetSymbolAddress((void**)&n_,    g_n);
    cudaGetSymbolAddress((void**)&a_,    g_a);
    cudaGetSymbolAddress((void**)&b_,    g_bp);
    cudaGetSymbolAddress((void**)&ql_,   g_ql);
    cudaGetSymbolAddress((void**)&qr_,   g_qr);
    cudaGetSymbolAddress((void**)&prev_, g_prev);
    cudaGetSymbolAddress((void**)&sd_,   g_sd);
    cudaGetSymbolAddress((void**)&pd_,   g_pd);
    cudaGetSymbolAddress((void**)&mix_,  g_mix);
    cudaGetSymbolAddress((void**)&r_,    g_r);
    cudaGetSymbolAddress((void**)&rn_,   g_rn);
    cudaGetSymbolAddress((void**)&h_,    g_h);
    cudaGetSymbolAddress((void**)&P_,    g_P);

    const int p2_smem = (4*4224 + 192) * 4;   // 68352 B
    cudaFuncSetAttribute(pair_phase2_kernel,
                         cudaFuncAttributeMaxDynamicSharedMemorySize, p2_smem);

    // 1) LN(x)
    ln_kernel<<<NTOK, 256>>>(x, ng, nb, n_);

    // 2) projections
    dim3 g512(512/64, NTOK/128);
    gemm_kernel<1, true,  false, false><<<g512, 256>>>(n_, Wa,  nullptr, nullptr, a_,  NTOK, 512, 512);
    gemm_kernel<1, true,  false, false><<<g512, 256>>>(n_, Wb,  nullptr, nullptr, b_,  NTOK, 512, 512);
    gemm_kernel<1, true,  false, false><<<g512, 256>>>(n_, Wql, nullptr, nullptr, ql_, NTOK, 512, 512);
    gemm_kernel<1, false, false, false><<<g512, 256>>>(n_, Wqr, nullptr, nullptr, qr_, NTOK, 512, 512);
    sdpd_kernel<<<NTOK/8, 256>>>(n_, Wsd, bsd, Wpd, bpd, sd_, pd_);

    // 3) scans (chunked)
    state_scan_kernel<<<NCH, 64>>>(a_, sd_, prev_);
    pair_phase1_kernel<<<NCH, 256>>>(prev_, b_, pd_, P_);
    pair_phase2_kernel<<<NCH*NCHUNK, 256, p2_smem>>>(prev_, b_, ql_, pd_, qr_, P_, mix_);

    // 4) r = x + mix @ Wout^T
    gemm_kernel<0, false, false, true><<<g512, 256>>>(mix_, Wout, nullptr, x, r_, NTOK, 512, 512);

    // 5) FFN
    ln_kernel<<<NTOK, 256>>>(r_, fg, fb, rn_);
    dim3 gW1(HID/64, NTOK/128);
    gemm_kernel<2, false, true, false><<<gW1, 256>>>(rn_, W1, b1, nullptr, h_, NTOK, HID, 512);
    dim3 gW2(512/64, NTOK/128);
    gemm_kernel<0, false, true, true><<<gW2, 256>>>(h_, W2, b2, r_, out, NTOK, 512, HID);
}

// round 9
// speedup vs baseline: 1.8104x; 1.4549x over previous
#include <cuda_runtime.h>
#include <math.h>
#include <stdint.h>

#define BB 8
#define SS 2048
#define DMODEL 512
#define HH 8
#define NTOK (BB*SS)      /* 16384 */
#define HID 2048
#define NCH (BB*HH)       /* 64 */
#define NCHUNK 32         /* 2048/64 */

typedef unsigned long long ull;

// ---------------- scratch (device globals: allocation-free rule) ----------------
__device__ float g_n   [NTOK*DMODEL];
__device__ float g_a   [NTOK*DMODEL];   // chain-major [B,H,S,64]
__device__ float g_bp  [NTOK*DMODEL];   // chain-major
__device__ float g_ql  [NTOK*DMODEL];   // chain-major
__device__ float g_qr  [NTOK*DMODEL];   // token-major [B,S,512]
__device__ float g_prev[NTOK*DMODEL];   // chain-major
__device__ float g_sd  [NCH*SS];
__device__ float g_pd  [NCH*SS];
__device__ float g_mix [NTOK*DMODEL];
__device__ float g_r   [NTOK*DMODEL];
__device__ float g_rn  [NTOK*DMODEL];
__device__ float g_h   [NTOK*HID];
__device__ float g_P   [(size_t)NCH*NCHUNK*64*64];

// ---------------- f32x2 packed helpers (sm_103a) ----------------
__device__ __forceinline__ ull pk2(float a, float b) {
    ull r; asm("mov.b64 %0, {%1, %2};" : "=l"(r) : "f"(a), "f"(b)); return r;
}
__device__ __forceinline__ void upk2(ull v, float& a, float& b) {
    asm("mov.b64 {%0, %1}, %2;" : "=f"(a), "=f"(b) : "l"(v));
}
__device__ __forceinline__ ull fma2(ull a, ull b, ull c) {
    ull d; asm("fma.rn.f32x2 %0, %1, %2, %3;" : "=l"(d) : "l"(a), "l"(b), "l"(c)); return d;
}
__device__ __forceinline__ ull mul2(ull a, ull b) {
    ull d; asm("mul.rn.f32x2 %0, %1, %2;" : "=l"(d) : "l"(a), "l"(b)); return d;
}

// ---------------- mma.sync bf16 + cp.async (base ISA, portable) ----------------
__device__ __forceinline__ uint32_t smem_u32(const void* p) {
    uint32_t a;
    asm("{ .reg .u64 t; cvta.to.shared.u64 t, %1; cvt.u32.u64 %0, t; }" : "=r"(a) : "l"(p));
    return a;
}
__device__ __forceinline__ void mma_bf16(float* c, const uint32_t* a, const uint32_t* b) {
    asm volatile(
        "mma.sync.aligned.m16n8k16.row.col.f32.bf16.bf16.f32 "
        "{%0,%1,%2,%3}, {%4,%5,%6,%7}, {%8,%9}, {%0,%1,%2,%3};\n"
        : "+f"(c[0]), "+f"(c[1]), "+f"(c[2]), "+f"(c[3])
        : "r"(a[0]), "r"(a[1]), "r"(a[2]), "r"(a[3]), "r"(b[0]), "r"(b[1]));
}
// split float2 -> bf16x2 hi + bf16x2 lo (lo = x - hi, exact in fp32)
__device__ __forceinline__ void split2(float2 v, uint32_t& hi, uint32_t& lo) {
    uint32_t h;
    asm("cvt.rn.bf16x2.f32 %0, %1, %2;" : "=r"(h) : "f"(v.y), "f"(v.x));
    float hx = __uint_as_float(h << 16);
    float hy = __uint_as_float(h & 0xFFFF0000u);
    float lx = v.x - hx, ly = v.y - hy;
    uint32_t l;
    asm("cvt.rn.bf16x2.f32 %0, %1, %2;" : "=r"(l) : "f"(ly), "f"(lx));
    hi = h; lo = l;
}
__device__ __forceinline__ void cp16(uint32_t dst, const void* src) {
    asm volatile("cp.async.cg.shared.global [%0], [%1], 16;" :: "r"(dst), "l"(src));
}
__device__ __forceinline__ void cp_commit() { asm volatile("cp.async.commit_group;" ::: "memory"); }
__device__ __forceinline__ void cp_wait1() { asm volatile("cp.async.wait_group 1;" ::: "memory"); }
__device__ __forceinline__ void cp_wait0() { asm volatile("cp.async.wait_group 0;" ::: "memory"); }

// ================= tensor-pipe GEMM (bf16x3): C = act(A[M,K] @ W[N,K]^T + bias)(+res) =======
// CTA tile 128x256, BK=32, 8 warps (2x4), warp tile 64x64. Double-buffered cp.async.
#define GM_MT 128
#define GM_NT 256
#define GM_KC 32
#define GM_AST 36            /* padded row stride (floats) */
#define GM_AFLT (GM_MT*GM_AST)       /* 4608 floats per A buf */
#define GM_BFLT (GM_NT*GM_AST)       /* 9216 floats per B buf */
#define GM_SMEM ((2*GM_AFLT + 2*GM_BFLT)*4)   /* 110592 B */

template<int ACT, bool SCAT, bool BIASF, bool RES>
__global__ __launch_bounds__(256, 1) void gemm_mma(
    const float* __restrict__ A, const float* __restrict__ W,
    const float* __restrict__ bias, const float* __restrict__ resid,
    float* __restrict__ C, int M, int N, int K)
{
    extern __shared__ __align__(16) float smf[];
    float* As = smf;                    // [2][128*36]
    float* Bs = smf + 2*GM_AFLT;        // [2][256*36]
    uint32_t sA = smem_u32(As), sB = smem_u32(Bs);

    int tid = threadIdx.x;
    int w = tid >> 5, lane = tid & 31;
    int g = lane >> 2, tig = lane & 3;
    int wr = w >> 2, wc = w & 3;
    int mW = wr * 64, nW = wc * 64;
    int m0 = blockIdx.y * GM_MT, n0 = blockIdx.x * GM_NT;

    float acc[4][8][4];
    #pragma unroll
    for (int i = 0; i < 4; i++)
        #pragma unroll
        for (int j = 0; j < 8; j++)
            #pragma unroll
            for (int r = 0; r < 4; r++) acc[i][j][r] = 0.f;

    const int NC = K / GM_KC;

    auto load_chunk = [&](int c, int buf) {
        const float* Ag = A + (size_t)m0 * K + (size_t)c * GM_KC;
        const float* Wg = W + (size_t)n0 * K + (size_t)c * GM_KC;
        uint32_t ab = sA + (uint32_t)buf * GM_AFLT * 4;
        uint32_t bb = sB + (uint32_t)buf * GM_BFLT * 4;
        #pragma unroll
        for (int p = 0; p < 4; p++) {
            int idx = p * 256 + tid;           // 0..1023
            int row = idx >> 3, kc = (idx & 7) * 4;
            cp16(ab + (uint32_t)(row * GM_AST + kc) * 4, Ag + (size_t)row * K + kc);
        }
        #pragma unroll
        for (int p = 0; p < 8; p++) {
            int idx = p * 256 + tid;           // 0..2047
            int row = idx >> 3, kc = (idx & 7) * 4;
            cp16(bb + (uint32_t)(row * GM_AST + kc) * 4, Wg + (size_t)row * K + kc);
        }
        cp_commit();
    };

    load_chunk(0, 0);

    for (int c = 0; c < NC; c++) {
        if (c + 1 < NC) { load_chunk(c + 1, (c + 1) & 1); cp_wait1(); }
        else cp_wait0();
        __syncthreads();
        const float* Asf = As + (c & 1) * GM_AFLT;
        const float* Bsf = Bs + (c & 1) * GM_BFLT;
        #pragma unroll
        for (int ks = 0; ks < 2; ks++) {      // two k16 slices per 32-k chunk
            int kb = ks * 16;
            // A fragments (m16n8k16): a0=(g,2tig) a1=(g+8,2tig) a2=(g,2tig+8) a3=(g+8,2tig+8)
            uint32_t ah[4][4], al[4][4];
            #pragma unroll
            for (int i = 0; i < 4; i++) {
                const float* base = Asf + (mW + 16*i + g) * GM_AST + kb + 2*tig;
                float2 x0 = *(const float2*)(base);
                float2 x1 = *(const float2*)(base + 8*GM_AST);
                float2 x2 = *(const float2*)(base + 8);
                float2 x3 = *(const float2*)(base + 8*GM_AST + 8);
                split2(x0, ah[i][0], al[i][0]);
                split2(x1, ah[i][1], al[i][1]);
                split2(x2, ah[i][2], al[i][2]);
                split2(x3, ah[i][3], al[i][3]);
            }
            #pragma unroll
            for (int j = 0; j < 8; j++) {
                // B fragments: b0=(k 2tig, n g) b1=(k 2tig+8, n g); W stored [n][k]
                const float* base = Bsf + (nW + 8*j + g) * GM_AST + kb + 2*tig;
                float2 y0 = *(const float2*)(base);
                float2 y1 = *(const float2*)(base + 8);
                uint32_t bh[2], bl[2];
                split2(y0, bh[0], bl[0]);
                split2(y1, bh[1], bl[1]);
                #pragma unroll
                for (int i = 0; i < 4; i++) {
                    mma_bf16(acc[i][j], ah[i], bh);
                    mma_bf16(acc[i][j], ah[i], bl);
                    mma_bf16(acc[i][j], al[i], bh);
                }
            }
        }
        __syncthreads();
    }

    // -------- epilogue: fragment layout c0..c3 --------
    #pragma unroll
    for (int i = 0; i < 4; i++) {
        #pragma unroll
        for (int half = 0; half < 2; half++) {
            int row = m0 + mW + 16*i + g + half*8;
            #pragma unroll
            for (int j = 0; j < 8; j++) {
                int col = n0 + nW + 8*j + 2*tig;
                float v0 = acc[i][j][half*2 + 0];
                float v1 = acc[i][j][half*2 + 1];
                if (BIASF) { v0 += __ldg(bias + col); v1 += __ldg(bias + col + 1); }
                if (ACT == 1) { v0 = tanhf(v0); v1 = tanhf(v1); }
                if (ACT == 2) {
                    v0 = 0.5f * v0 * (1.0f + erff(v0 * 0.70710678118654752f));
                    v1 = 0.5f * v1 * (1.0f + erff(v1 * 0.70710678118654752f));
                }
                if (RES) {
                    float2 rv = *(const float2*)(resid + (size_t)row * N + col);
                    v0 += rv.x; v1 += rv.y;
                }
                size_t base;
                if (SCAT) {
                    base = ((size_t)((row >> 11) * HH + (col >> 6))) * ((size_t)SS * 64)
                         + (size_t)(row & (SS - 1)) * 64 + (size_t)(col & 63);
                } else {
                    base = (size_t)row * N + col;
                }
                *(float2*)(C + base) = make_float2(v0, v1);
            }
        }
    }
}

// ---------------- LayerNorm ----------------
__global__ __launch_bounds__(256) void ln_kernel(
    const float* __restrict__ X, const float* __restrict__ G,
    const float* __restrict__ Bt, float* __restrict__ O)
{
    int row = blockIdx.x;
    int tid = threadIdx.x;
    const float* xr = X + (size_t)row*DMODEL;
    float2 v = *(const float2*)(xr + tid*2);
    float s  = v.x + v.y;
    float ss = v.x*v.x + v.y*v.y;
    #pragma unroll
    for (int m = 16; m > 0; m >>= 1) {
        s  += __shfl_xor_sync(0xffffffffu, s,  m);
        ss += __shfl_xor_sync(0xffffffffu, ss, m);
    }
    __shared__ float shs[8], shss[8];
    int w = tid >> 5, l = tid & 31;
    if (l == 0) { shs[w] = s; shss[w] = ss; }
    __syncthreads();
    if (tid == 0) {
        float S_ = 0.f, SS_ = 0.f;
        #pragma unroll
        for (int i = 0; i < 8; i++) { S_ += shs[i]; SS_ += shss[i]; }
        shs[0] = S_; shss[0] = SS_;
    }
    __syncthreads();
    float mean = shs[0] * (1.0f/DMODEL);
    float var  = shss[0] * (1.0f/DMODEL) - mean*mean;
    float inv  = rsqrtf(var + 1e-5f);
    float2 gv = *(const float2*)(G  + tid*2);
    float2 bv = *(const float2*)(Bt + tid*2);
    float2 o;
    o.x = (v.x - mean)*inv*gv.x + bv.x;
    o.y = (v.y - mean)*inv*gv.y + bv.y;
    *(float2*)(O + (size_t)row*DMODEL + tid*2) = o;
}

// ---------------- sd/pd gates ----------------
__global__ __launch_bounds__(256) void sdpd_kernel(
    const float* __restrict__ Nn, const float* __restrict__ Wsd, const float* __restrict__ bsd,
    const float* __restrict__ Wpd, const float* __restrict__ bpd,
    float* __restrict__ sd_o, float* __restrict__ pd_o)
{
    __shared__ float Wsh[16][512];
    __shared__ float nsh[512];
    int tid = threadIdx.x;
    #pragma unroll
    for (int k = 0; k < 32; k++) {
        int idx = tid + 256*k;
        float v = (idx < 4096) ? Wsd[idx] : Wpd[idx - 4096];
        Wsh[idx >> 9][idx & 511] = v;
    }
    int o = tid >> 4, p = tid & 15;
    float bias_v = (o < 8) ? __ldg(bsd + o) : __ldg(bpd + o - 8);
    for (int tk = 0; tk < 8; tk++) {
        int token = blockIdx.x*8 + tk;
        __syncthreads();
        nsh[tid]       = Nn[(size_t)token*512 + tid];
        nsh[tid + 256] = Nn[(size_t)token*512 + tid + 256];
        __syncthreads();
        float s = 0.f;
        #pragma unroll
        for (int i = 0; i < 32; i++) {
            int d = i*16 + p;
            s += nsh[d] * Wsh[o][d];
        }
        s += __shfl_xor_sync(0xffffffffu, s, 8);
        s += __shfl_xor_sync(0xffffffffu, s, 4);
        s += __shfl_xor_sync(0xffffffffu, s, 2);
        s += __shfl_xor_sync(0xffffffffu, s, 1);
        if (p == 0) {
            float z = s + bias_v;
            float sg = 1.0f / (1.0f + expf(-z));
            int b = token >> 11, t = token & (SS-1);
            int h = o & 7;
            size_t oi = ((size_t)(b*8 + h))*SS + t;
            if (o < 8) sd_o[oi] = sg; else pd_o[oi] = sg;
        }
    }
}

// ---------------- state scan ----------------
__global__ __launch_bounds__(64) void state_scan_kernel(
    const float* __restrict__ a, const float* __restrict__ sd, float* __restrict__ prev)
{
    int chain = blockIdx.x, tid = threadIdx.x;
    const float* aP  = a  + (size_t)chain*SS*64;
    const float* sdP = sd + (size_t)chain*SS;
    float* pP        = prev + (size_t)chain*SS*64;
    float st = 0.0f;
    for (int t0 = 0; t0 < SS; t0 += 8) {
        float av[8], sv[8];
        #pragma unroll
        for (int j = 0; j < 8; j++) av[j] = aP[(size_t)(t0+j)*64 + tid];
        #pragma unroll
        for (int j = 0; j < 8; j++) sv[j] = __ldg(sdP + t0 + j);
        #pragma unroll
        for (int j = 0; j < 8; j++) {
            pP[(size_t)(t0+j)*64 + tid] = st;
            st = sv[j]*st + (1.0f - sv[j])*av[j];
        }
    }
}

// ---------------- chunked pair recurrence, phase 1 ----------------
__global__ __launch_bounds__(256) void pair_phase1_kernel(
    const float* __restrict__ prevA, const float* __restrict__ bA,
    const float* __restrict__ pdA, float* __restrict__ Psnap)
{
    int chain = blockIdx.x;
    const float* prevC = prevA + (size_t)chain*SS*64;
    const float* bC    = bA    + (size_t)chain*SS*64;
    const float* pdC   = pdA   + (size_t)chain*SS;
    __shared__ float prev_s[64*66];
    __shared__ float b_s[64*66];
    __shared__ float sh_pd[64], sh_cp[64], sh_u[64];
    int tid = threadIdx.x;
    int d0 = (tid >> 4) * 4, e0 = (tid & 15) * 4;
    int r = tid >> 2, cc = (tid & 3) * 16;

    ull p2[4][2];
    #pragma unroll
    for (int i = 0; i < 4; i++) { p2[i][0] = 0ULL; p2[i][1] = 0ULL; }

    for (int c = 0; c < NCHUNK; c++) {
        __syncthreads();
        {
            const float* gp = prevC + ((size_t)c*64 + r)*64 + cc;
            const float* gb = bC    + ((size_t)c*64 + r)*64 + cc;
            #pragma unroll
            for (int q = 0; q < 4; q++) {
                float4 v = *(const float4*)(gp + q*4);
                *(float2*)&prev_s[r*66 + cc + q*4    ] = make_float2(v.x, v.y);
                *(float2*)&prev_s[r*66 + cc + q*4 + 2] = make_float2(v.z, v.w);
                float4 u = *(const float4*)(gb + q*4);
                *(float2*)&b_s[r*66 + cc + q*4    ] = make_float2(u.x, u.y);
                *(float2*)&b_s[r*66 + cc + q*4 + 2] = make_float2(u.z, u.w);
            }
            if (tid < 64) sh_pd[tid] = pdC[c*64 + tid];
        }
        __syncthreads();
        if (tid == 0) {
            float cp = 1.0f;
            for (int j = 0; j < 64; j++) { cp = fmaxf(cp * sh_pd[j], 1e-35f); sh_cp[j] = cp; }
        }
        __syncthreads();
        if (tid < 64) sh_u[tid] = (1.0f - sh_pd[tid]) * (sh_cp[63] / sh_cp[tid]);
        float* Pc = Psnap + (((size_t)chain*NCHUNK + c)*64)*64;
        #pragma unroll
        for (int i = 0; i < 4; i++) {
            float l0, h0, l1, h1;
            upk2(p2[i][0], l0, h0); upk2(p2[i][1], l1, h1);
            float4 v = make_float4(l0, h0, l1, h1);
            *(float4*)(Pc + (size_t)(d0+i)*64 + e0) = v;
        }
        __syncthreads();
        float cpE = sh_cp[63];
        ull cpE2 = pk2(cpE, cpE);
        #pragma unroll
        for (int i = 0; i < 4; i++) {
            p2[i][0] = mul2(p2[i][0], cpE2);
            p2[i][1] = mul2(p2[i][1], cpE2);
        }
        for (int j = 0; j < 64; j++) {
            float uj = sh_u[j];
            ull b20 = *(const ull*)&b_s[j*66 + e0];
            ull b21 = *(const ull*)&b_s[j*66 + e0 + 2];
            #pragma unroll
            for (int i = 0; i < 4; i++) {
                float s = uj * prev_s[j*66 + d0 + i];
                ull s2 = pk2(s, s);
                p2[i][0] = fma2(s2, b20, p2[i][0]);
                p2[i][1] = fma2(s2, b21, p2[i][1]);
            }
        }
    }
}

// ---------------- chunked pair, phase 2 ----------------
__global__ __launch_bounds__(256) void pair_phase2_kernel(
    const float* __restrict__ prevA, const float* __restrict__ bA,
    const float* __restrict__ qlA,   const float* __restrict__ pdA,
    const float* __restrict__ qrA,   const float* __restrict__ Psnap,
    float* __restrict__ mixA)
{
    int blk = blockIdx.x;
    int chain = blk >> 5, c = blk & 31;
    int bb = chain >> 3, hh = chain & 7;
    const float* prevC = prevA + (size_t)chain*SS*64;
    const float* bC    = bA    + (size_t)chain*SS*64;
    const float* qlC   = qlA   + (size_t)chain*SS*64;
    const float* pdC   = pdA   + (size_t)chain*SS;
    const float* Pc    = Psnap + (((size_t)chain*NCHUNK + c)*64)*64;

    extern __shared__ float sm[];
    float* ql_s = sm;
    float* pw_s = sm + 4224;
    float* b_s  = sm + 8448;
    float* P_s  = sm + 12672;
    float* sh_pd  = sm + 16896;
    float* sh_cp  = sh_pd + 64;
    float* sh_inv = sh_cp + 64;

    int tid = threadIdx.x;
    int r = tid >> 2, cc = (tid & 3) * 16;
    {
        const float* gq = qlC   + ((size_t)c*64 + r)*64 + cc;
        const float* gp = prevC + ((size_t)c*64 + r)*64 + cc;
        const float* gb = bC    + ((size_t)c*64 + r)*64 + cc;
        const float* gP = Pc    + (size_t)r*64 + cc;
        #pragma unroll
        for (int q = 0; q < 4; q++) {
            float4 v;
            v = *(const float4*)(gq + q*4);
            *(float2*)&ql_s[r*66 + cc + q*4    ] = make_float2(v.x, v.y);
            *(float2*)&ql_s[r*66 + cc + q*4 + 2] = make_float2(v.z, v.w);
            v = *(const float4*)(gp + q*4);
            *(float2*)&pw_s[r*66 + cc + q*4    ] = make_float2(v.x, v.y);
            *(float2*)&pw_s[r*66 + cc + q*4 + 2] = make_float2(v.z, v.w);
            v = *(const float4*)(gb + q*4);
            *(float2*)&b_s[r*66 + cc + q*4    ] = make_float2(v.x, v.y);
            *(float2*)&b_s[r*66 + cc + q*4 + 2] = make_float2(v.z, v.w);
            v = *(const float4*)(gP + q*4);
            *(float2*)&P_s[r*66 + cc + q*4    ] = make_float2(v.x, v.y);
            *(float2*)&P_s[r*66 + cc + q*4 + 2] = make_float2(v.z, v.w);
        }
        if (tid < 64) sh_pd[tid] = pdC[c*64 + tid];
    }
    __syncthreads();
    if (tid == 0) {
        float cp = 1.0f;
        for (int j = 0; j < 64; j++) { cp = fmaxf(cp * sh_pd[j], 1e-35f); sh_cp[j] = cp; }
    }
    __syncthreads();
    if (tid < 64) sh_inv[tid] = 1.0f / sh_cp[tid];

    int t0 = (tid >> 4) * 4, j0 = (tid & 15) * 4;
    ull g2[4][4];
    #pragma unroll
    for (int i = 0; i < 4; i++)
        #pragma unroll
        for (int j = 0; j < 4; j++) g2[i][j] = 0ULL;
    #pragma unroll 8
    for (int kp = 0; kp < 32; kp++) {
        ull aq[4], pj[4];
        #pragma unroll
        for (int i = 0; i < 4; i++) aq[i] = *(const ull*)&ql_s[(t0+i)*66 + 2*kp];
        #pragma unroll
        for (int j = 0; j < 4; j++) pj[j] = *(const ull*)&pw_s[(j0+j)*66 + 2*kp];
        #pragma unroll
        for (int i = 0; i < 4; i++)
            #pragma unroll
            for (int j = 0; j < 4; j++)
                g2[i][j] = fma2(aq[i], pj[j], g2[i][j]);
    }
    float wv[4][4];
    #pragma unroll
    for (int i = 0; i < 4; i++) {
        int tt = t0 + i;
        float cpt = sh_cp[tt];
        #pragma unroll
        for (int j = 0; j < 4; j++) {
            int jj = j0 + j;
            float lo, hi; upk2(g2[i][j], lo, hi);
            float coef = (jj <= tt) ? (1.0f - sh_pd[jj]) * cpt * sh_inv[jj] : 0.0f;
            wv[i][j] = (lo + hi) * coef;
        }
    }
    __syncthreads();
    #pragma unroll
    for (int i = 0; i < 4; i++)
        #pragma unroll
        for (int j = 0; j < 4; j++)
            pw_s[(t0+i)*66 + (j0+j)] = wv[i][j];
    __syncthreads();

    int e0 = j0;
    ull lc2[4][2], st2[4][2];
    #pragma unroll
    for (int i = 0; i < 4; i++) { lc2[i][0]=lc2[i][1]=st2[i][0]=st2[i][1]=0ULL; }
    for (int j = 0; j < 64; j++) {
        ull b20 = *(const ull*)&b_s[j*66 + e0];
        ull b21 = *(const ull*)&b_s[j*66 + e0 + 2];
        ull P20 = *(const ull*)&P_s[j*66 + e0];
        ull P21 = *(const ull*)&P_s[j*66 + e0 + 2];
        #pragma unroll
        for (int i = 0; i < 4; i++) {
            float w = pw_s[(t0+i)*66 + j];
            ull w2 = pk2(w, w);
            lc2[i][0] = fma2(w2, b20, lc2[i][0]);
            lc2[i][1] = fma2(w2, b21, lc2[i][1]);
            float q = ql_s[(t0+i)*66 + j];
            ull q2 = pk2(q, q);
            st2[i][0] = fma2(q2, P20, st2[i][0]);
            st2[i][1] = fma2(q2, P21, st2[i][1]);
        }
    }
    #pragma unroll
    for (int i = 0; i < 4; i++) {
        float cpt = sh_cp[t0 + i];
        ull cp2 = pk2(cpt, cpt);
        ull r0 = fma2(cp2, st2[i][0], lc2[i][0]);
        ull r1 = fma2(cp2, st2[i][1], lc2[i][1]);
        float l0, h0, l1, h1;
        upk2(r0, l0, h0); upk2(r1, l1, h1);
        int tglob = c*64 + t0 + i;
        size_t oo = ((size_t)bb*SS + tglob)*DMODEL + (size_t)hh*64 + e0;
        float4 qr4 = *(const float4*)(qrA + oo);
        float4 ov = make_float4(l0*qr4.x, h0*qr4.y, l1*qr4.z, h1*qr4.w);
        *(float4*)(mixA + oo) = ov;
    }
}

// ---------------- host ----------------
extern "C" void kernel_launch(void* const* d_in, const int* in_sizes, int n_in,
                              void* d_out, int out_size)
{
    const float* x    = (const float*)d_in[0];
    const float* ng   = (const float*)d_in[1];
    const float* nb   = (const float*)d_in[2];
    const float* fg   = (const float*)d_in[3];
    const float* fb   = (const float*)d_in[4];
    const float* Wa   = (const float*)d_in[5];
    const float* Wb   = (const float*)d_in[6];
    const float* Wql  = (const float*)d_in[7];
    const float* Wqr  = (const float*)d_in[8];
    const float* Wsd  = (const float*)d_in[9];
    const float* bsd  = (const float*)d_in[10];
    const float* Wpd  = (const float*)d_in[11];
    const float* bpd  = (const float*)d_in[12];
    const float* Wout = (const float*)d_in[13];
    const float* W1   = (const float*)d_in[14];
    const float* b1   = (const float*)d_in[15];
    const float* W2   = (const float*)d_in[16];
    const float* b2   = (const float*)d_in[17];
    float* out = (float*)d_out;

    float *n_, *a_, *b_, *ql_, *qr_, *prev_, *sd_, *pd_, *mix_, *r_, *rn_, *h_, *P_;
    cudaGetSymbolAddress((void**)&n_,    g_n);
    cudaGetSymbolAddress((void**)&a_,    g_a);
    cudaGetSymbolAddress((void**)&b_,    g_bp);
    cudaGetSymbolAddress((void**)&ql_,   g_ql);
    cudaGetSymbolAddress((void**)&qr_,   g_qr);
    cudaGetSymbolAddress((void**)&prev_, g_prev);
    cudaGetSymbolAddress((void**)&sd_,   g_sd);
    cudaGetSymbolAddress((void**)&pd_,   g_pd);
    cudaGetSymbolAddress((void**)&mix_,  g_mix);
    cudaGetSymbolAddress((void**)&r_,    g_r);
    cudaGetSymbolAddress((void**)&rn_,   g_rn);
    cudaGetSymbolAddress((void**)&h_,    g_h);
    cudaGetSymbolAddress((void**)&P_,    g_P);

    const int p2_smem = (4*4224 + 192) * 4;
    cudaFuncSetAttribute(pair_phase2_kernel,
                         cudaFuncAttributeMaxDynamicSharedMemorySize, p2_smem);
    cudaFuncSetAttribute(gemm_mma<1,true,false,false>,
                         cudaFuncAttributeMaxDynamicSharedMemorySize, GM_SMEM);
    cudaFuncSetAttribute(gemm_mma<1,false,false,false>,
                         cudaFuncAttributeMaxDynamicSharedMemorySize, GM_SMEM);
    cudaFuncSetAttribute(gemm_mma<0,false,false,true>,
                         cudaFuncAttributeMaxDynamicSharedMemorySize, GM_SMEM);
    cudaFuncSetAttribute(gemm_mma<2,false,true,false>,
                         cudaFuncAttributeMaxDynamicSharedMemorySize, GM_SMEM);
    cudaFuncSetAttribute(gemm_mma<0,false,true,true>,
                         cudaFuncAttributeMaxDynamicSharedMemorySize, GM_SMEM);

    // 1) LN(x)
    ln_kernel<<<NTOK, 256>>>(x, ng, nb, n_);

    // 2) projections (tensor pipe, bf16x3) — ALL FOUR get tanh (ACT=1)
    dim3 gP512(512/GM_NT, NTOK/GM_MT);
    gemm_mma<1,true, false,false><<<gP512, 256, GM_SMEM>>>(n_, Wa,  nullptr, nullptr, a_,  NTOK, 512, 512);
    gemm_mma<1,true, false,false><<<gP512, 256, GM_SMEM>>>(n_, Wb,  nullptr, nullptr, b_,  NTOK, 512, 512);
    gemm_mma<1,true, false,false><<<gP512, 256, GM_SMEM>>>(n_, Wql, nullptr, nullptr, ql_, NTOK, 512, 512);
    gemm_mma<1,false,false,false><<<gP512, 256, GM_SMEM>>>(n_, Wqr, nullptr, nullptr, qr_, NTOK, 512, 512);
    sdpd_kernel<<<NTOK/8, 256>>>(n_, Wsd, bsd, Wpd, bpd, sd_, pd_);

    // 3) scans (chunked)
    state_scan_kernel<<<NCH, 64>>>(a_, sd_, prev_);
    pair_phase1_kernel<<<NCH, 256>>>(prev_, b_, pd_, P_);
    pair_phase2_kernel<<<NCH*NCHUNK, 256, p2_smem>>>(prev_, b_, ql_, pd_, qr_, P_, mix_);

    // 4) r = x + mix @ Wout^T
    gemm_mma<0,false,false,true><<<gP512, 256, GM_SMEM>>>(mix_, Wout, nullptr, x, r_, NTOK, 512, 512);

    // 5) FFN
    ln_kernel<<<NTOK, 256>>>(r_, fg, fb, rn_);
    dim3 gW1(HID/GM_NT, NTOK/GM_MT);
    gemm_mma<2,false,true,false><<<gW1, 256, GM_SMEM>>>(rn_, W1, b1, nullptr, h_, NTOK, HID, 512);
    dim3 gW2(512/GM_NT, NTOK/GM_MT);
    gemm_mma<0,false,true,true><<<gW2, 256, GM_SMEM>>>(h_, W2, b2, r_, out, NTOK, 512, HID);
}

// round 10
// speedup vs baseline: 3.3778x; 1.8657x over previous
#include <cuda_runtime.h>
#include <math.h>
#include <stdint.h>

#define BB 8
#define SS 2048
#define DMODEL 512
#define HH 8
#define NTOK (BB*SS)      /* 16384 */
#define HID 2048
#define NCH (BB*HH)       /* 64 */
#define NCHUNK 32         /* 2048/64 */

typedef unsigned long long ull;

// ---------------- scratch (device globals: allocation-free rule) ----------------
__device__ float g_n   [NTOK*DMODEL];
__device__ float g_a   [NTOK*DMODEL];   // chain-major [B,H,S,64]
__device__ float g_bp  [NTOK*DMODEL];   // chain-major
__device__ float g_ql  [NTOK*DMODEL];   // chain-major
__device__ float g_qr  [NTOK*DMODEL];   // token-major [B,S,512]
__device__ float g_prev[NTOK*DMODEL];   // chain-major
__device__ float g_sd  [NCH*SS];
__device__ float g_pd  [NCH*SS];
__device__ float g_mix [NTOK*DMODEL];
__device__ float g_r   [NTOK*DMODEL];
__device__ float g_rn  [NTOK*DMODEL];
__device__ float g_h   [NTOK*HID];
__device__ float g_P   [(size_t)NCH*NCHUNK*64*64];

// ---------------- f32x2 packed helpers (sm_103a) ----------------
__device__ __forceinline__ ull pk2(float a, float b) {
    ull r; asm("mov.b64 %0, {%1, %2};" : "=l"(r) : "f"(a), "f"(b)); return r;
}
__device__ __forceinline__ void upk2(ull v, float& a, float& b) {
    asm("mov.b64 {%0, %1}, %2;" : "=f"(a), "=f"(b) : "l"(v));
}
__device__ __forceinline__ ull fma2(ull a, ull b, ull c) {
    ull d; asm("fma.rn.f32x2 %0, %1, %2, %3;" : "=l"(d) : "l"(a), "l"(b), "l"(c)); return d;
}
__device__ __forceinline__ ull mul2(ull a, ull b) {
    ull d; asm("mul.rn.f32x2 %0, %1, %2;" : "=l"(d) : "l"(a), "l"(b)); return d;
}

// ---------------- mma.sync tf32 + cp.async (base ISA, portable) ----------------
__device__ __forceinline__ uint32_t smem_u32(const void* p) {
    uint32_t a;
    asm("{ .reg .u64 t; cvta.to.shared.u64 t, %1; cvt.u32.u64 %0, t; }" : "=r"(a) : "l"(p));
    return a;
}
__device__ __forceinline__ void mma_tf32(float* c, const uint32_t* a, const uint32_t* b) {
    asm volatile(
        "mma.sync.aligned.m16n8k8.row.col.f32.tf32.tf32.f32 "
        "{%0,%1,%2,%3}, {%4,%5,%6,%7}, {%8,%9}, {%0,%1,%2,%3};\n"
        : "+f"(c[0]), "+f"(c[1]), "+f"(c[2]), "+f"(c[3])
        : "r"(a[0]), "r"(a[1]), "r"(a[2]), "r"(a[3]), "r"(b[0]), "r"(b[1]));
}
// fp32 -> tf32 with round-to-nearest (avoids truncation bias)
__device__ __forceinline__ uint32_t f2tf(float x) {
    uint32_t r;
    asm("cvt.rna.tf32.f32 %0, %1;" : "=r"(r) : "f"(x));
    return r;
}
__device__ __forceinline__ void cp16(uint32_t dst, const void* src) {
    asm volatile("cp.async.cg.shared.global [%0], [%1], 16;" :: "r"(dst), "l"(src));
}
__device__ __forceinline__ void cp_commit() { asm volatile("cp.async.commit_group;" ::: "memory"); }
__device__ __forceinline__ void cp_wait1() { asm volatile("cp.async.wait_group 1;" ::: "memory"); }
__device__ __forceinline__ void cp_wait0() { asm volatile("cp.async.wait_group 0;" ::: "memory"); }

// ================= tensor-pipe GEMM (tf32): C = act(A[M,K] @ W[N,K]^T + bias)(+res) =======
// CTA tile 128x256, BK=32, 8 warps (2x4), warp tile 64x64. Double-buffered cp.async.
#define GM_MT 128
#define GM_NT 256
#define GM_KC 32
#define GM_AST 36            /* padded row stride (floats) */
#define GM_AFLT (GM_MT*GM_AST)       /* 4608 floats per A buf */
#define GM_BFLT (GM_NT*GM_AST)       /* 9216 floats per B buf */
#define GM_SMEM ((2*GM_AFLT + 2*GM_BFLT)*4)   /* 110592 B */

template<int ACT, bool SCAT, bool BIASF, bool RES>
__global__ __launch_bounds__(256, 1) void gemm_mma(
    const float* __restrict__ A, const float* __restrict__ W,
    const float* __restrict__ bias, const float* __restrict__ resid,
    float* __restrict__ C, int M, int N, int K)
{
    extern __shared__ __align__(16) float smf[];
    float* As = smf;                    // [2][128*36]
    float* Bs = smf + 2*GM_AFLT;        // [2][256*36]
    uint32_t sA = smem_u32(As), sB = smem_u32(Bs);

    int tid = threadIdx.x;
    int w = tid >> 5, lane = tid & 31;
    int g = lane >> 2, tig = lane & 3;
    int wr = w >> 2, wc = w & 3;
    int mW = wr * 64, nW = wc * 64;
    int m0 = blockIdx.y * GM_MT, n0 = blockIdx.x * GM_NT;

    float acc[4][8][4];
    #pragma unroll
    for (int i = 0; i < 4; i++)
        #pragma unroll
        for (int j = 0; j < 8; j++)
            #pragma unroll
            for (int r = 0; r < 4; r++) acc[i][j][r] = 0.f;

    const int NC = K / GM_KC;

    auto load_chunk = [&](int c, int buf) {
        const float* Ag = A + (size_t)m0 * K + (size_t)c * GM_KC;
        const float* Wg = W + (size_t)n0 * K + (size_t)c * GM_KC;
        uint32_t ab = sA + (uint32_t)buf * GM_AFLT * 4;
        uint32_t bb = sB + (uint32_t)buf * GM_BFLT * 4;
        #pragma unroll
        for (int p = 0; p < 4; p++) {
            int idx = p * 256 + tid;           // 0..1023
            int row = idx >> 3, kc = (idx & 7) * 4;
            cp16(ab + (uint32_t)(row * GM_AST + kc) * 4, Ag + (size_t)row * K + kc);
        }
        #pragma unroll
        for (int p = 0; p < 8; p++) {
            int idx = p * 256 + tid;           // 0..2047
            int row = idx >> 3, kc = (idx & 7) * 4;
            cp16(bb + (uint32_t)(row * GM_AST + kc) * 4, Wg + (size_t)row * K + kc);
        }
        cp_commit();
    };

    load_chunk(0, 0);

    for (int c = 0; c < NC; c++) {
        if (c + 1 < NC) { load_chunk(c + 1, (c + 1) & 1); cp_wait1(); }
        else cp_wait0();
        __syncthreads();
        const float* Asf = As + (c & 1) * GM_AFLT;
        const float* Bsf = Bs + (c & 1) * GM_BFLT;
        #pragma unroll
        for (int ks = 0; ks < 4; ks++) {      // four k8 slices per 32-k chunk
            int kb = ks * 8;
            // A fragments (m16n8k8): a0=(g,tig) a1=(g+8,tig) a2=(g,tig+4) a3=(g+8,tig+4)
            uint32_t af[4][4];
            #pragma unroll
            for (int i = 0; i < 4; i++) {
                const float* base = Asf + (mW + 16*i + g) * GM_AST + kb + tig;
                af[i][0] = f2tf(base[0]);
                af[i][1] = f2tf(base[8*GM_AST]);
                af[i][2] = f2tf(base[4]);
                af[i][3] = f2tf(base[8*GM_AST + 4]);
            }
            uint32_t bf[8][2];
            #pragma unroll
            for (int j = 0; j < 8; j++) {
                const float* base = Bsf + (nW + 8*j + g) * GM_AST + kb + tig;
                bf[j][0] = f2tf(base[0]);
                bf[j][1] = f2tf(base[4]);
            }
            #pragma unroll
            for (int i = 0; i < 4; i++)
                #pragma unroll
                for (int j = 0; j < 8; j++)
                    mma_tf32(acc[i][j], af[i], bf[j]);
        }
        __syncthreads();
    }

    // -------- epilogue: fragment layout c0..c3 --------
    #pragma unroll
    for (int i = 0; i < 4; i++) {
        #pragma unroll
        for (int half = 0; half < 2; half++) {
            int row = m0 + mW + 16*i + g + half*8;
            #pragma unroll
            for (int j = 0; j < 8; j++) {
                int col = n0 + nW + 8*j + 2*tig;
                float v0 = acc[i][j][half*2 + 0];
                float v1 = acc[i][j][half*2 + 1];
                if (BIASF) { v0 += __ldg(bias + col); v1 += __ldg(bias + col + 1); }
                if (ACT == 1) { v0 = tanhf(v0); v1 = tanhf(v1); }
                if (ACT == 2) {
                    v0 = 0.5f * v0 * (1.0f + erff(v0 * 0.70710678118654752f));
                    v1 = 0.5f * v1 * (1.0f + erff(v1 * 0.70710678118654752f));
                }
                if (RES) {
                    float2 rv = *(const float2*)(resid + (size_t)row * N + col);
                    v0 += rv.x; v1 += rv.y;
                }
                size_t base;
                if (SCAT) {
                    base = ((size_t)((row >> 11) * HH + (col >> 6))) * ((size_t)SS * 64)
                         + (size_t)(row & (SS - 1)) * 64 + (size_t)(col & 63);
                } else {
                    base = (size_t)row * N + col;
                }
                *(float2*)(C + base) = make_float2(v0, v1);
            }
        }
    }
}

// ---------------- LayerNorm ----------------
__global__ __launch_bounds__(256) void ln_kernel(
    const float* __restrict__ X, const float* __restrict__ G,
    const float* __restrict__ Bt, float* __restrict__ O)
{
    int row = blockIdx.x;
    int tid = threadIdx.x;
    const float* xr = X + (size_t)row*DMODEL;
    float2 v = *(const float2*)(xr + tid*2);
    float s  = v.x + v.y;
    float ss = v.x*v.x + v.y*v.y;
    #pragma unroll
    for (int m = 16; m > 0; m >>= 1) {
        s  += __shfl_xor_sync(0xffffffffu, s,  m);
        ss += __shfl_xor_sync(0xffffffffu, ss, m);
    }
    __shared__ float shs[8], shss[8];
    int w = tid >> 5, l = tid & 31;
    if (l == 0) { shs[w] = s; shss[w] = ss; }
    __syncthreads();
    if (tid == 0) {
        float S_ = 0.f, SS_ = 0.f;
        #pragma unroll
        for (int i = 0; i < 8; i++) { S_ += shs[i]; SS_ += shss[i]; }
        shs[0] = S_; shss[0] = SS_;
    }
    __syncthreads();
    float mean = shs[0] * (1.0f/DMODEL);
    float var  = shss[0] * (1.0f/DMODEL) - mean*mean;
    float inv  = rsqrtf(var + 1e-5f);
    float2 gv = *(const float2*)(G  + tid*2);
    float2 bv = *(const float2*)(Bt + tid*2);
    float2 o;
    o.x = (v.x - mean)*inv*gv.x + bv.x;
    o.y = (v.y - mean)*inv*gv.y + bv.y;
    *(float2*)(O + (size_t)row*DMODEL + tid*2) = o;
}

// ---------------- sd/pd gates ----------------
__global__ __launch_bounds__(256) void sdpd_kernel(
    const float* __restrict__ Nn, const float* __restrict__ Wsd, const float* __restrict__ bsd,
    const float* __restrict__ Wpd, const float* __restrict__ bpd,
    float* __restrict__ sd_o, float* __restrict__ pd_o)
{
    __shared__ float Wsh[16][512];
    __shared__ float nsh[512];
    int tid = threadIdx.x;
    #pragma unroll
    for (int k = 0; k < 32; k++) {
        int idx = tid + 256*k;
        float v = (idx < 4096) ? Wsd[idx] : Wpd[idx - 4096];
        Wsh[idx >> 9][idx & 511] = v;
    }
    int o = tid >> 4, p = tid & 15;
    float bias_v = (o < 8) ? __ldg(bsd + o) : __ldg(bpd + o - 8);
    for (int tk = 0; tk < 8; tk++) {
        int token = blockIdx.x*8 + tk;
        __syncthreads();
        nsh[tid]       = Nn[(size_t)token*512 + tid];
        nsh[tid + 256] = Nn[(size_t)token*512 + tid + 256];
        __syncthreads();
        float s = 0.f;
        #pragma unroll
        for (int i = 0; i < 32; i++) {
            int d = i*16 + p;
            s += nsh[d] * Wsh[o][d];
        }
        s += __shfl_xor_sync(0xffffffffu, s, 8);
        s += __shfl_xor_sync(0xffffffffu, s, 4);
        s += __shfl_xor_sync(0xffffffffu, s, 2);
        s += __shfl_xor_sync(0xffffffffu, s, 1);
        if (p == 0) {
            float z = s + bias_v;
            float sg = 1.0f / (1.0f + expf(-z));
            int b = token >> 11, t = token & (SS-1);
            int h = o & 7;
            size_t oi = ((size_t)(b*8 + h))*SS + t;
            if (o < 8) sd_o[oi] = sg; else pd_o[oi] = sg;
        }
    }
}

// ---------------- state scan ----------------
__global__ __launch_bounds__(64) void state_scan_kernel(
    const float* __restrict__ a, const float* __restrict__ sd, float* __restrict__ prev)
{
    int chain = blockIdx.x, tid = threadIdx.x;
    const float* aP  = a  + (size_t)chain*SS*64;
    const float* sdP = sd + (size_t)chain*SS;
    float* pP        = prev + (size_t)chain*SS*64;
    float st = 0.0f;
    for (int t0 = 0; t0 < SS; t0 += 8) {
        float av[8], sv[8];
        #pragma unroll
        for (int j = 0; j < 8; j++) av[j] = aP[(size_t)(t0+j)*64 + tid];
        #pragma unroll
        for (int j = 0; j < 8; j++) sv[j] = __ldg(sdP + t0 + j);
        #pragma unroll
        for (int j = 0; j < 8; j++) {
            pP[(size_t)(t0+j)*64 + tid] = st;
            st = sv[j]*st + (1.0f - sv[j])*av[j];
        }
    }
}

// ---------------- chunked pair recurrence, phase 1 ----------------
__global__ __launch_bounds__(256) void pair_phase1_kernel(
    const float* __restrict__ prevA, const float* __restrict__ bA,
    const float* __restrict__ pdA, float* __restrict__ Psnap)
{
    int chain = blockIdx.x;
    const float* prevC = prevA + (size_t)chain*SS*64;
    const float* bC    = bA    + (size_t)chain*SS*64;
    const float* pdC   = pdA   + (size_t)chain*SS;
    __shared__ float prev_s[64*66];
    __shared__ float b_s[64*66];
    __shared__ float sh_pd[64], sh_cp[64], sh_u[64];
    int tid = threadIdx.x;
    int d0 = (tid >> 4) * 4, e0 = (tid & 15) * 4;
    int r = tid >> 2, cc = (tid & 3) * 16;

    ull p2[4][2];
    #pragma unroll
    for (int i = 0; i < 4; i++) { p2[i][0] = 0ULL; p2[i][1] = 0ULL; }

    for (int c = 0; c < NCHUNK; c++) {
        __syncthreads();
        {
            const float* gp = prevC + ((size_t)c*64 + r)*64 + cc;
            const float* gb = bC    + ((size_t)c*64 + r)*64 + cc;
            #pragma unroll
            for (int q = 0; q < 4; q++) {
                float4 v = *(const float4*)(gp + q*4);
                *(float2*)&prev_s[r*66 + cc + q*4    ] = make_float2(v.x, v.y);
                *(float2*)&prev_s[r*66 + cc + q*4 + 2] = make_float2(v.z, v.w);
                float4 u = *(const float4*)(gb + q*4);
                *(float2*)&b_s[r*66 + cc + q*4    ] = make_float2(u.x, u.y);
                *(float2*)&b_s[r*66 + cc + q*4 + 2] = make_float2(u.z, u.w);
            }
            if (tid < 64) sh_pd[tid] = pdC[c*64 + tid];
        }
        __syncthreads();
        if (tid == 0) {
            float cp = 1.0f;
            for (int j = 0; j < 64; j++) { cp = fmaxf(cp * sh_pd[j], 1e-35f); sh_cp[j] = cp; }
        }
        __syncthreads();
        if (tid < 64) sh_u[tid] = (1.0f - sh_pd[tid]) * (sh_cp[63] / sh_cp[tid]);
        float* Pc = Psnap + (((size_t)chain*NCHUNK + c)*64)*64;
        #pragma unroll
        for (int i = 0; i < 4; i++) {
            float l0, h0, l1, h1;
            upk2(p2[i][0], l0, h0); upk2(p2[i][1], l1, h1);
            float4 v = make_float4(l0, h0, l1, h1);
            *(float4*)(Pc + (size_t)(d0+i)*64 + e0) = v;
        }
        __syncthreads();
        float cpE = sh_cp[63];
        ull cpE2 = pk2(cpE, cpE);
        #pragma unroll
        for (int i = 0; i < 4; i++) {
            p2[i][0] = mul2(p2[i][0], cpE2);
            p2[i][1] = mul2(p2[i][1], cpE2);
        }
        for (int j = 0; j < 64; j++) {
            float uj = sh_u[j];
            ull b20 = *(const ull*)&b_s[j*66 + e0];
            ull b21 = *(const ull*)&b_s[j*66 + e0 + 2];
            #pragma unroll
            for (int i = 0; i < 4; i++) {
                float s = uj * prev_s[j*66 + d0 + i];
                ull s2 = pk2(s, s);
                p2[i][0] = fma2(s2, b20, p2[i][0]);
                p2[i][1] = fma2(s2, b21, p2[i][1]);
            }
        }
    }
}

// ---------------- chunked pair, phase 2 ----------------
__global__ __launch_bounds__(256) void pair_phase2_kernel(
    const float* __restrict__ prevA, const float* __restrict__ bA,
    const float* __restrict__ qlA,   const float* __restrict__ pdA,
    const float* __restrict__ qrA,   const float* __restrict__ Psnap,
    float* __restrict__ mixA)
{
    int blk = blockIdx.x;
    int chain = blk >> 5, c = blk & 31;
    int bb = chain >> 3, hh = chain & 7;
    const float* prevC = prevA + (size_t)chain*SS*64;
    const float* bC    = bA    + (size_t)chain*SS*64;
    const float* qlC   = qlA   + (size_t)chain*SS*64;
    const float* pdC   = pdA   + (size_t)chain*SS;
    const float* Pc    = Psnap + (((size_t)chain*NCHUNK + c)*64)*64;

    extern __shared__ float sm[];
    float* ql_s = sm;
    float* pw_s = sm + 4224;
    float* b_s  = sm + 8448;
    float* P_s  = sm + 12672;
    float* sh_pd  = sm + 16896;
    float* sh_cp  = sh_pd + 64;
    float* sh_inv = sh_cp + 64;

    int tid = threadIdx.x;
    int r = tid >> 2, cc = (tid & 3) * 16;
    {
        const float* gq = qlC   + ((size_t)c*64 + r)*64 + cc;
        const float* gp = prevC + ((size_t)c*64 + r)*64 + cc;
        const float* gb = bC    + ((size_t)c*64 + r)*64 + cc;
        const float* gP = Pc    + (size_t)r*64 + cc;
        #pragma unroll
        for (int q = 0; q < 4; q++) {
            float4 v;
            v = *(const float4*)(gq + q*4);
            *(float2*)&ql_s[r*66 + cc + q*4    ] = make_float2(v.x, v.y);
            *(float2*)&ql_s[r*66 + cc + q*4 + 2] = make_float2(v.z, v.w);
            v = *(const float4*)(gp + q*4);
            *(float2*)&pw_s[r*66 + cc + q*4    ] = make_float2(v.x, v.y);
            *(float2*)&pw_s[r*66 + cc + q*4 + 2] = make_float2(v.z, v.w);
            v = *(const float4*)(gb + q*4);
            *(float2*)&b_s[r*66 + cc + q*4    ] = make_float2(v.x, v.y);
            *(float2*)&b_s[r*66 + cc + q*4 + 2] = make_float2(v.z, v.w);
            v = *(const float4*)(gP + q*4);
            *(float2*)&P_s[r*66 + cc + q*4    ] = make_float2(v.x, v.y);
            *(float2*)&P_s[r*66 + cc + q*4 + 2] = make_float2(v.z, v.w);
        }
        if (tid < 64) sh_pd[tid] = pdC[c*64 + tid];
    }
    __syncthreads();
    if (tid == 0) {
        float cp = 1.0f;
        for (int j = 0; j < 64; j++) { cp = fmaxf(cp * sh_pd[j], 1e-35f); sh_cp[j] = cp; }
    }
    __syncthreads();
    if (tid < 64) sh_inv[tid] = 1.0f / sh_cp[tid];

    int t0 = (tid >> 4) * 4, j0 = (tid & 15) * 4;
    ull g2[4][4];
    #pragma unroll
    for (int i = 0; i < 4; i++)
        #pragma unroll
        for (int j = 0; j < 4; j++) g2[i][j] = 0ULL;
    #pragma unroll 8
    for (int kp = 0; kp < 32; kp++) {
        ull aq[4], pj[4];
        #pragma unroll
        for (int i = 0; i < 4; i++) aq[i] = *(const ull*)&ql_s[(t0+i)*66 + 2*kp];
        #pragma unroll
        for (int j = 0; j < 4; j++) pj[j] = *(const ull*)&pw_s[(j0+j)*66 + 2*kp];
        #pragma unroll
        for (int i = 0; i < 4; i++)
            #pragma unroll
            for (int j = 0; j < 4; j++)
                g2[i][j] = fma2(aq[i], pj[j], g2[i][j]);
    }
    float wv[4][4];
    #pragma unroll
    for (int i = 0; i < 4; i++) {
        int tt = t0 + i;
        float cpt = sh_cp[tt];
        #pragma unroll
        for (int j = 0; j < 4; j++) {
            int jj = j0 + j;
            float lo, hi; upk2(g2[i][j], lo, hi);
            float coef = (jj <= tt) ? (1.0f - sh_pd[jj]) * cpt * sh_inv[jj] : 0.0f;
            wv[i][j] = (lo + hi) * coef;
        }
    }
    __syncthreads();
    #pragma unroll
    for (int i = 0; i < 4; i++)
        #pragma unroll
        for (int j = 0; j < 4; j++)
            pw_s[(t0+i)*66 + (j0+j)] = wv[i][j];
    __syncthreads();

    int e0 = j0;
    ull lc2[4][2], st2[4][2];
    #pragma unroll
    for (int i = 0; i < 4; i++) { lc2[i][0]=lc2[i][1]=st2[i][0]=st2[i][1]=0ULL; }
    for (int j = 0; j < 64; j++) {
        ull b20 = *(const ull*)&b_s[j*66 + e0];
        ull b21 = *(const ull*)&b_s[j*66 + e0 + 2];
        ull P20 = *(const ull*)&P_s[j*66 + e0];
        ull P21 = *(const ull*)&P_s[j*66 + e0 + 2];
        #pragma unroll
        for (int i = 0; i < 4; i++) {
            float w = pw_s[(t0+i)*66 + j];
            ull w2 = pk2(w, w);
            lc2[i][0] = fma2(w2, b20, lc2[i][0]);
            lc2[i][1] = fma2(w2, b21, lc2[i][1]);
            float q = ql_s[(t0+i)*66 + j];
            ull q2 = pk2(q, q);
            st2[i][0] = fma2(q2, P20, st2[i][0]);
            st2[i][1] = fma2(q2, P21, st2[i][1]);
        }
    }
    #pragma unroll
    for (int i = 0; i < 4; i++) {
        float cpt = sh_cp[t0 + i];
        ull cp2 = pk2(cpt, cpt);
        ull r0 = fma2(cp2, st2[i][0], lc2[i][0]);
        ull r1 = fma2(cp2, st2[i][1], lc2[i][1]);
        float l0, h0, l1, h1;
        upk2(r0, l0, h0); upk2(r1, l1, h1);
        int tglob = c*64 + t0 + i;
        size_t oo = ((size_t)bb*SS + tglob)*DMODEL + (size_t)hh*64 + e0;
        float4 qr4 = *(const float4*)(qrA + oo);
        float4 ov = make_float4(l0*qr4.x, h0*qr4.y, l1*qr4.z, h1*qr4.w);
        *(float4*)(mixA + oo) = ov;
    }
}

// ---------------- host ----------------
extern "C" void kernel_launch(void* const* d_in, const int* in_sizes, int n_in,
                              void* d_out, int out_size)
{
    const float* x    = (const float*)d_in[0];
    const float* ng   = (const float*)d_in[1];
    const float* nb   = (const float*)d_in[2];
    const float* fg   = (const float*)d_in[3];
    const float* fb   = (const float*)d_in[4];
    const float* Wa   = (const float*)d_in[5];
    const float* Wb   = (const float*)d_in[6];
    const float* Wql  = (const float*)d_in[7];
    const float* Wqr  = (const float*)d_in[8];
    const float* Wsd  = (const float*)d_in[9];
    const float* bsd  = (const float*)d_in[10];
    const float* Wpd  = (const float*)d_in[11];
    const float* bpd  = (const float*)d_in[12];
    const float* Wout = (const float*)d_in[13];
    const float* W1   = (const float*)d_in[14];
    const float* b1   = (const float*)d_in[15];
    const float* W2   = (const float*)d_in[16];
    const float* b2   = (const float*)d_in[17];
    float* out = (float*)d_out;

    float *n_, *a_, *b_, *ql_, *qr_, *prev_, *sd_, *pd_, *mix_, *r_, *rn_, *h_, *P_;
    cudaGetSymbolAddress((void**)&n_,    g_n);
    cudaGetSymbolAddress((void**)&a_,    g_a);
    cudaGetSymbolAddress((void**)&b_,    g_bp);
    cudaGetSymbolAddress((void**)&ql_,   g_ql);
    cudaGetSymbolAddress((void**)&qr_,   g_qr);
    cudaGetSymbolAddress((void**)&prev_, g_prev);
    cudaGetSymbolAddress((void**)&sd_,   g_sd);
    cudaGetSymbolAddress((void**)&pd_,   g_pd);
    cudaGetSymbolAddress((void**)&mix_,  g_mix);
    cudaGetSymbolAddress((void**)&r_,    g_r);
    cudaGetSymbolAddress((void**)&rn_,   g_rn);
    cudaGetSymbolAddress((void**)&h_,    g_h);
    cudaGetSymbolAddress((void**)&P_,    g_P);

    const int p2_smem = (4*4224 + 192) * 4;
    cudaFuncSetAttribute(pair_phase2_kernel,
                         cudaFuncAttributeMaxDynamicSharedMemorySize, p2_smem);
    cudaFuncSetAttribute(gemm_mma<1,true,false,false>,
                         cudaFuncAttributeMaxDynamicSharedMemorySize, GM_SMEM);
    cudaFuncSetAttribute(gemm_mma<1,false,false,false>,
                         cudaFuncAttributeMaxDynamicSharedMemorySize, GM_SMEM);
    cudaFuncSetAttribute(gemm_mma<0,false,false,true>,
                         cudaFuncAttributeMaxDynamicSharedMemorySize, GM_SMEM);
    cudaFuncSetAttribute(gemm_mma<2,false,true,false>,
                         cudaFuncAttributeMaxDynamicSharedMemorySize, GM_SMEM);
    cudaFuncSetAttribute(gemm_mma<0,false,true,true>,
                         cudaFuncAttributeMaxDynamicSharedMemorySize, GM_SMEM);

    // 1) LN(x)
    ln_kernel<<<NTOK, 256>>>(x, ng, nb, n_);

    // 2) projections (tensor pipe, tf32 rounded) — ALL FOUR get tanh (ACT=1)
    dim3 gP512(512/GM_NT, NTOK/GM_MT);
    gemm_mma<1,true, false,false><<<gP512, 256, GM_SMEM>>>(n_, Wa,  nullptr, nullptr, a_,  NTOK, 512, 512);
    gemm_mma<1,true, false,false><<<gP512, 256, GM_SMEM>>>(n_, Wb,  nullptr, nullptr, b_,  NTOK, 512, 512);
    gemm_mma<1,true, false,false><<<gP512, 256, GM_SMEM>>>(n_, Wql, nullptr, nullptr, ql_, NTOK, 512, 512);
    gemm_mma<1,false,false,false><<<gP512, 256, GM_SMEM>>>(n_, Wqr, nullptr, nullptr, qr_, NTOK, 512, 512);
    sdpd_kernel<<<NTOK/8, 256>>>(n_, Wsd, bsd, Wpd, bpd, sd_, pd_);

    // 3) scans (chunked)
    state_scan_kernel<<<NCH, 64>>>(a_, sd_, prev_);
    pair_phase1_kernel<<<NCH, 256>>>(prev_, b_, pd_, P_);
    pair_phase2_kernel<<<NCH*NCHUNK, 256, p2_smem>>>(prev_, b_, ql_, pd_, qr_, P_, mix_);

    // 4) r = x + mix @ Wout^T
    gemm_mma<0,false,false,true><<<gP512, 256, GM_SMEM>>>(mix_, Wout, nullptr, x, r_, NTOK, 512, 512);

    // 5) FFN
    ln_kernel<<<NTOK, 256>>>(r_, fg, fb, rn_);
    dim3 gW1(HID/GM_NT, NTOK/GM_MT);
    gemm_mma<2,false,true,false><<<gW1, 256, GM_SMEM>>>(rn_, W1, b1, nullptr, h_, NTOK, HID, 512);
    dim3 gW2(512/GM_NT, NTOK/GM_MT);
    gemm_mma<0,false,true,true><<<gW2, 256, GM_SMEM>>>(h_, W2, b2, r_, out, NTOK, 512, HID);
}

// round 11
// speedup vs baseline: 3.6031x; 1.0667x over previous
#include <cuda_runtime.h>
#include <math.h>
#include <stdint.h>

#define BB 8
#define SS 2048
#define DMODEL 512
#define HH 8
#define NTOK (BB*SS)      /* 16384 */
#define HID 2048
#define NCH (BB*HH)       /* 64 */
#define NCHUNK 32         /* 2048/64 */

typedef unsigned long long ull;

// rounded-weight scratch offsets (floats)
#define OFF_WA   0
#define OFF_WB   262144
#define OFF_WQL  524288
#define OFF_WQR  786432
#define OFF_WOUT 1048576
#define OFF_W1   1310720
#define OFF_W2   2359296
#define W_TOTAL  3407872

// ---------------- scratch (device globals: allocation-free rule) ----------------
__device__ float g_n   [NTOK*DMODEL];
__device__ float g_a   [NTOK*DMODEL];   // chain-major [B,H,S,64]
__device__ float g_bp  [NTOK*DMODEL];   // chain-major
__device__ float g_ql  [NTOK*DMODEL];   // chain-major
__device__ float g_qr  [NTOK*DMODEL];   // token-major [B,S,512]
__device__ float g_prev[NTOK*DMODEL];   // chain-major
__device__ float g_sd  [NCH*SS];
__device__ float g_pd  [NCH*SS];
__device__ float g_mix [NTOK*DMODEL];
__device__ float g_r   [NTOK*DMODEL];
__device__ float g_rn  [NTOK*DMODEL];
__device__ float g_h   [NTOK*HID];
__device__ float g_P   [(size_t)NCH*NCHUNK*64*64];
__device__ float g_wr  [W_TOTAL];       // tf32-rounded weights

// ---------------- f32x2 packed helpers (sm_103a) ----------------
__device__ __forceinline__ ull pk2(float a, float b) {
    ull r; asm("mov.b64 %0, {%1, %2};" : "=l"(r) : "f"(a), "f"(b)); return r;
}
__device__ __forceinline__ void upk2(ull v, float& a, float& b) {
    asm("mov.b64 {%0, %1}, %2;" : "=f"(a), "=f"(b) : "l"(v));
}
__device__ __forceinline__ ull fma2(ull a, ull b, ull c) {
    ull d; asm("fma.rn.f32x2 %0, %1, %2, %3;" : "=l"(d) : "l"(a), "l"(b), "l"(c)); return d;
}
__device__ __forceinline__ ull mul2(ull a, ull b) {
    ull d; asm("mul.rn.f32x2 %0, %1, %2;" : "=l"(d) : "l"(a), "l"(b)); return d;
}

// ---------------- mma.sync tf32 + cp.async (base ISA, portable) ----------------
__device__ __forceinline__ uint32_t smem_u32(const void* p) {
    uint32_t a;
    asm("{ .reg .u64 t; cvta.to.shared.u64 t, %1; cvt.u32.u64 %0, t; }" : "=r"(a) : "l"(p));
    return a;
}
__device__ __forceinline__ void mma_tf32(float* c, const uint32_t* a, const uint32_t* b) {
    asm volatile(
        "mma.sync.aligned.m16n8k8.row.col.f32.tf32.tf32.f32 "
        "{%0,%1,%2,%3}, {%4,%5,%6,%7}, {%8,%9}, {%0,%1,%2,%3};\n"
        : "+f"(c[0]), "+f"(c[1]), "+f"(c[2]), "+f"(c[3])
        : "r"(a[0]), "r"(a[1]), "r"(a[2]), "r"(a[3]), "r"(b[0]), "r"(b[1]));
}
// fp32 -> tf32 with round-to-nearest (bit pattern is fp32 with low mantissa zeroed)
__device__ __forceinline__ uint32_t f2tf(float x) {
    uint32_t r;
    asm("cvt.rna.tf32.f32 %0, %1;" : "=r"(r) : "f"(x));
    return r;
}
__device__ __forceinline__ float roundtf(float x) { return __uint_as_float(f2tf(x)); }
__device__ __forceinline__ void cp16(uint32_t dst, const void* src) {
    asm volatile("cp.async.cg.shared.global [%0], [%1], 16;" :: "r"(dst), "l"(src));
}
__device__ __forceinline__ void cp_commit() { asm volatile("cp.async.commit_group;" ::: "memory"); }
__device__ __forceinline__ void cp_wait1() { asm volatile("cp.async.wait_group 1;" ::: "memory"); }
__device__ __forceinline__ void cp_wait0() { asm volatile("cp.async.wait_group 0;" ::: "memory"); }

// ---------------- weight pre-round pass ----------------
__global__ __launch_bounds__(256) void round_w_kernel(
    const float* __restrict__ Wa, const float* __restrict__ Wb,
    const float* __restrict__ Wql, const float* __restrict__ Wqr,
    const float* __restrict__ Wout, const float* __restrict__ W1,
    const float* __restrict__ W2, float* __restrict__ dst)
{
    int i = blockIdx.x * 256 + threadIdx.x;
    int stride = gridDim.x * 256;
    for (; i < W_TOTAL; i += stride) {
        const float* s; int off;
        if      (i < OFF_WB)   { s = Wa;   off = i; }
        else if (i < OFF_WQL)  { s = Wb;   off = i - OFF_WB; }
        else if (i < OFF_WQR)  { s = Wql;  off = i - OFF_WQL; }
        else if (i < OFF_WOUT) { s = Wqr;  off = i - OFF_WQR; }
        else if (i < OFF_W1)   { s = Wout; off = i - OFF_WOUT; }
        else if (i < OFF_W2)   { s = W1;   off = i - OFF_W1; }
        else                   { s = W2;   off = i - OFF_W2; }
        dst[i] = roundtf(s[off]);
    }
}

// ================= tensor-pipe GEMM (tf32, pre-rounded operands) =================
// CTA tile 128x256, BK=32, 8 warps (2x4), warp tile 64x64. Double-buffered cp.async.
#define GM_MT 128
#define GM_NT 256
#define GM_KC 32
#define GM_AST 36            /* padded row stride (floats) */
#define GM_AFLT (GM_MT*GM_AST)       /* 4608 floats per A buf */
#define GM_BFLT (GM_NT*GM_AST)       /* 9216 floats per B buf */
#define GM_SMEM ((2*GM_AFLT + 2*GM_BFLT)*4)   /* 110592 B */

template<int ACT, bool BIASF, bool RES, bool RND>
__device__ __forceinline__ void gemm_body(
    const float* __restrict__ A, const float* __restrict__ W,
    const float* __restrict__ bias, const float* __restrict__ resid,
    float* __restrict__ C, int N, int K, int m0, int n0, bool scat,
    float* smf)
{
    float* As = smf;                    // [2][128*36]
    float* Bs = smf + 2*GM_AFLT;        // [2][256*36]
    uint32_t sA = smem_u32(As), sB = smem_u32(Bs);

    int tid = threadIdx.x;
    int w = tid >> 5, lane = tid & 31;
    int g = lane >> 2, tig = lane & 3;
    int wr = w >> 2, wc = w & 3;
    int mW = wr * 64, nW = wc * 64;

    float acc[4][8][4];
    #pragma unroll
    for (int i = 0; i < 4; i++)
        #pragma unroll
        for (int j = 0; j < 8; j++)
            #pragma unroll
            for (int r = 0; r < 4; r++) acc[i][j][r] = 0.f;

    const int NC = K / GM_KC;

    auto load_chunk = [&](int c, int buf) {
        const float* Ag = A + (size_t)m0 * K + (size_t)c * GM_KC;
        const float* Wg = W + (size_t)n0 * K + (size_t)c * GM_KC;
        uint32_t ab = sA + (uint32_t)buf * GM_AFLT * 4;
        uint32_t bb = sB + (uint32_t)buf * GM_BFLT * 4;
        #pragma unroll
        for (int p = 0; p < 4; p++) {
            int idx = p * 256 + tid;           // 0..1023
            int row = idx >> 3, kc = (idx & 7) * 4;
            cp16(ab + (uint32_t)(row * GM_AST + kc) * 4, Ag + (size_t)row * K + kc);
        }
        #pragma unroll
        for (int p = 0; p < 8; p++) {
            int idx = p * 256 + tid;           // 0..2047
            int row = idx >> 3, kc = (idx & 7) * 4;
            cp16(bb + (uint32_t)(row * GM_AST + kc) * 4, Wg + (size_t)row * K + kc);
        }
        cp_commit();
    };

    load_chunk(0, 0);

    for (int c = 0; c < NC; c++) {
        if (c + 1 < NC) { load_chunk(c + 1, (c + 1) & 1); cp_wait1(); }
        else cp_wait0();
        __syncthreads();
        const uint32_t* Au = (const uint32_t*)(As + (c & 1) * GM_AFLT);
        const uint32_t* Bu = (const uint32_t*)(Bs + (c & 1) * GM_BFLT);
        // hoist all A fragments for the chunk (operands pre-rounded: no cvt)
        uint32_t af[4][4][4];
        #pragma unroll
        for (int ks = 0; ks < 4; ks++) {
            int kb = ks * 8;
            #pragma unroll
            for (int i = 0; i < 4; i++) {
                const uint32_t* base = Au + (mW + 16*i + g) * GM_AST + kb + tig;
                af[ks][i][0] = base[0];
                af[ks][i][1] = base[8*GM_AST];
                af[ks][i][2] = base[4];
                af[ks][i][3] = base[8*GM_AST + 4];
            }
        }
        #pragma unroll
        for (int ks = 0; ks < 4; ks++) {
            int kb = ks * 8;
            uint32_t bf[8][2];
            #pragma unroll
            for (int j = 0; j < 8; j++) {
                const uint32_t* base = Bu + (nW + 8*j + g) * GM_AST + kb + tig;
                bf[j][0] = base[0];
                bf[j][1] = base[4];
            }
            #pragma unroll
            for (int i = 0; i < 4; i++)
                #pragma unroll
                for (int j = 0; j < 8; j++)
                    mma_tf32(acc[i][j], af[ks][i], bf[j]);
        }
        __syncthreads();
    }

    // -------- epilogue --------
    #pragma unroll
    for (int i = 0; i < 4; i++) {
        #pragma unroll
        for (int half = 0; half < 2; half++) {
            int row = m0 + mW + 16*i + g + half*8;
            #pragma unroll
            for (int j = 0; j < 8; j++) {
                int col = n0 + nW + 8*j + 2*tig;
                float v0 = acc[i][j][half*2 + 0];
                float v1 = acc[i][j][half*2 + 1];
                if (BIASF) { v0 += __ldg(bias + col); v1 += __ldg(bias + col + 1); }
                if (ACT == 1) { v0 = tanhf(v0); v1 = tanhf(v1); }
                if (ACT == 2) {
                    v0 = 0.5f * v0 * (1.0f + erff(v0 * 0.70710678118654752f));
                    v1 = 0.5f * v1 * (1.0f + erff(v1 * 0.70710678118654752f));
                }
                if (RES) {
                    float2 rv = *(const float2*)(resid + (size_t)row * N + col);
                    v0 += rv.x; v1 += rv.y;
                }
                if (RND) { v0 = roundtf(v0); v1 = roundtf(v1); }
                size_t base;
                if (scat) {
                    base = ((size_t)((row >> 11) * HH + (col >> 6))) * ((size_t)SS * 64)
                         + (size_t)(row & (SS - 1)) * 64 + (size_t)(col & 63);
                } else {
                    base = (size_t)row * N + col;
                }
                *(float2*)(C + base) = make_float2(v0, v1);
            }
        }
    }
}

template<int ACT, bool BIASF, bool RES, bool RND>
__global__ __launch_bounds__(256, 1) void gemm_mma(
    const float* __restrict__ A, const float* __restrict__ W,
    const float* __restrict__ bias, const float* __restrict__ resid,
    float* __restrict__ C, int M, int N, int K)
{
    extern __shared__ __align__(16) float smf[];
    gemm_body<ACT, BIASF, RES, RND>(A, W, bias, resid, C, N, K,
                                    blockIdx.y * GM_MT, blockIdx.x * GM_NT, false, smf);
}

// fused 4-way projection: grid.x = 8 (wsel = bx>>1, n-half = bx&1), grid.y = 128
__global__ __launch_bounds__(256, 1) void proj_mma(
    const float* __restrict__ A, const float* __restrict__ Wr,
    float* __restrict__ a_o, float* __restrict__ b_o,
    float* __restrict__ ql_o, float* __restrict__ qr_o)
{
    extern __shared__ __align__(16) float smf[];
    int wsel = blockIdx.x >> 1;
    int n0 = (blockIdx.x & 1) * GM_NT;
    const float* W = Wr + (size_t)wsel * 262144;
    float* C = (wsel == 0) ? a_o : (wsel == 1) ? b_o : (wsel == 2) ? ql_o : qr_o;
    bool scat = (wsel < 3);
    gemm_body<1, false, false, false>(A, W, nullptr, nullptr, C, 512, 512,
                                      blockIdx.y * GM_MT, n0, scat, smf);
}

// ---------------- LayerNorm (tf32-rounded output) ----------------
__global__ __launch_bounds__(256) void ln_kernel(
    const float* __restrict__ X, const float* __restrict__ G,
    const float* __restrict__ Bt, float* __restrict__ O)
{
    int row = blockIdx.x;
    int tid = threadIdx.x;
    const float* xr = X + (size_t)row*DMODEL;
    float2 v = *(const float2*)(xr + tid*2);
    float s  = v.x + v.y;
    float ss = v.x*v.x + v.y*v.y;
    #pragma unroll
    for (int m = 16; m > 0; m >>= 1) {
        s  += __shfl_xor_sync(0xffffffffu, s,  m);
        ss += __shfl_xor_sync(0xffffffffu, ss, m);
    }
    __shared__ float shs[8], shss[8];
    int w = tid >> 5, l = tid & 31;
    if (l == 0) { shs[w] = s; shss[w] = ss; }
    __syncthreads();
    if (tid == 0) {
        float S_ = 0.f, SS_ = 0.f;
        #pragma unroll
        for (int i = 0; i < 8; i++) { S_ += shs[i]; SS_ += shss[i]; }
        shs[0] = S_; shss[0] = SS_;
    }
    __syncthreads();
    float mean = shs[0] * (1.0f/DMODEL);
    float var  = shss[0] * (1.0f/DMODEL) - mean*mean;
    float inv  = rsqrtf(var + 1e-5f);
    float2 gv = *(const float2*)(G  + tid*2);
    float2 bv = *(const float2*)(Bt + tid*2);
    float2 o;
    o.x = roundtf((v.x - mean)*inv*gv.x + bv.x);
    o.y = roundtf((v.y - mean)*inv*gv.y + bv.y);
    *(float2*)(O + (size_t)row*DMODEL + tid*2) = o;
}

// ---------------- sd/pd gates ----------------
__global__ __launch_bounds__(256) void sdpd_kernel(
    const float* __restrict__ Nn, const float* __restrict__ Wsd, const float* __restrict__ bsd,
    const float* __restrict__ Wpd, const float* __restrict__ bpd,
    float* __restrict__ sd_o, float* __restrict__ pd_o)
{
    __shared__ float Wsh[16][512];
    __shared__ float nsh[512];
    int tid = threadIdx.x;
    #pragma unroll
    for (int k = 0; k < 32; k++) {
        int idx = tid + 256*k;
        float v = (idx < 4096) ? Wsd[idx] : Wpd[idx - 4096];
        Wsh[idx >> 9][idx & 511] = v;
    }
    int o = tid >> 4, p = tid & 15;
    float bias_v = (o < 8) ? __ldg(bsd + o) : __ldg(bpd + o - 8);
    for (int tk = 0; tk < 8; tk++) {
        int token = blockIdx.x*8 + tk;
        __syncthreads();
        nsh[tid]       = Nn[(size_t)token*512 + tid];
        nsh[tid + 256] = Nn[(size_t)token*512 + tid + 256];
        __syncthreads();
        float s = 0.f;
        #pragma unroll
        for (int i = 0; i < 32; i++) {
            int d = i*16 + p;
            s += nsh[d] * Wsh[o][d];
        }
        s += __shfl_xor_sync(0xffffffffu, s, 8);
        s += __shfl_xor_sync(0xffffffffu, s, 4);
        s += __shfl_xor_sync(0xffffffffu, s, 2);
        s += __shfl_xor_sync(0xffffffffu, s, 1);
        if (p == 0) {
            float z = s + bias_v;
            float sg = 1.0f / (1.0f + expf(-z));
            int b = token >> 11, t = token & (SS-1);
            int h = o & 7;
            size_t oi = ((size_t)(b*8 + h))*SS + t;
            if (o < 8) sd_o[oi] = sg; else pd_o[oi] = sg;
        }
    }
}

// ---------------- state scan ----------------
__global__ __launch_bounds__(64) void state_scan_kernel(
    const float* __restrict__ a, const float* __restrict__ sd, float* __restrict__ prev)
{
    int chain = blockIdx.x, tid = threadIdx.x;
    const float* aP  = a  + (size_t)chain*SS*64;
    const float* sdP = sd + (size_t)chain*SS;
    float* pP        = prev + (size_t)chain*SS*64;
    float st = 0.0f;
    for (int t0 = 0; t0 < SS; t0 += 8) {
        float av[8], sv[8];
        #pragma unroll
        for (int j = 0; j < 8; j++) av[j] = aP[(size_t)(t0+j)*64 + tid];
        #pragma unroll
        for (int j = 0; j < 8; j++) sv[j] = __ldg(sdP + t0 + j);
        #pragma unroll
        for (int j = 0; j < 8; j++) {
            pP[(size_t)(t0+j)*64 + tid] = st;
            st = sv[j]*st + (1.0f - sv[j])*av[j];
        }
    }
}

// ---------------- chunked pair recurrence, phase 1 ----------------
__global__ __launch_bounds__(256) void pair_phase1_kernel(
    const float* __restrict__ prevA, const float* __restrict__ bA,
    const float* __restrict__ pdA, float* __restrict__ Psnap)
{
    int chain = blockIdx.x;
    const float* prevC = prevA + (size_t)chain*SS*64;
    const float* bC    = bA    + (size_t)chain*SS*64;
    const float* pdC   = pdA   + (size_t)chain*SS;
    __shared__ float prev_s[64*66];
    __shared__ float b_s[64*66];
    __shared__ float sh_pd[64], sh_cp[64], sh_u[64];
    int tid = threadIdx.x;
    int d0 = (tid >> 4) * 4, e0 = (tid & 15) * 4;
    int r = tid >> 2, cc = (tid & 3) * 16;

    ull p2[4][2];
    #pragma unroll
    for (int i = 0; i < 4; i++) { p2[i][0] = 0ULL; p2[i][1] = 0ULL; }

    for (int c = 0; c < NCHUNK; c++) {
        __syncthreads();
        {
            const float* gp = prevC + ((size_t)c*64 + r)*64 + cc;
            const float* gb = bC    + ((size_t)c*64 + r)*64 + cc;
            #pragma unroll
            for (int q = 0; q < 4; q++) {
                float4 v = *(const float4*)(gp + q*4);
                *(float2*)&prev_s[r*66 + cc + q*4    ] = make_float2(v.x, v.y);
                *(float2*)&prev_s[r*66 + cc + q*4 + 2] = make_float2(v.z, v.w);
                float4 u = *(const float4*)(gb + q*4);
                *(float2*)&b_s[r*66 + cc + q*4    ] = make_float2(u.x, u.y);
                *(float2*)&b_s[r*66 + cc + q*4 + 2] = make_float2(u.z, u.w);
            }
            if (tid < 64) sh_pd[tid] = pdC[c*64 + tid];
        }
        __syncthreads();
        if (tid == 0) {
            float cp = 1.0f;
            for (int j = 0; j < 64; j++) { cp = fmaxf(cp * sh_pd[j], 1e-35f); sh_cp[j] = cp; }
        }
        __syncthreads();
        if (tid < 64) sh_u[tid] = (1.0f - sh_pd[tid]) * (sh_cp[63] / sh_cp[tid]);
        float* Pc = Psnap + (((size_t)chain*NCHUNK + c)*64)*64;
        #pragma unroll
        for (int i = 0; i < 4; i++) {
            float l0, h0, l1, h1;
            upk2(p2[i][0], l0, h0); upk2(p2[i][1], l1, h1);
            float4 v = make_float4(l0, h0, l1, h1);
            *(float4*)(Pc + (size_t)(d0+i)*64 + e0) = v;
        }
        __syncthreads();
        float cpE = sh_cp[63];
        ull cpE2 = pk2(cpE, cpE);
        #pragma unroll
        for (int i = 0; i < 4; i++) {
            p2[i][0] = mul2(p2[i][0], cpE2);
            p2[i][1] = mul2(p2[i][1], cpE2);
        }
        for (int j = 0; j < 64; j++) {
            float uj = sh_u[j];
            ull b20 = *(const ull*)&b_s[j*66 + e0];
            ull b21 = *(const ull*)&b_s[j*66 + e0 + 2];
            #pragma unroll
            for (int i = 0; i < 4; i++) {
                float s = uj * prev_s[j*66 + d0 + i];
                ull s2 = pk2(s, s);
                p2[i][0] = fma2(s2, b20, p2[i][0]);
                p2[i][1] = fma2(s2, b21, p2[i][1]);
            }
        }
    }
}

// ---------------- chunked pair, phase 2 (mix rounded for Wout GEMM) ----------------
__global__ __launch_bounds__(256) void pair_phase2_kernel(
    const float* __restrict__ prevA, const float* __restrict__ bA,
    const float* __restrict__ qlA,   const float* __restrict__ pdA,
    const float* __restrict__ qrA,   const float* __restrict__ Psnap,
    float* __restrict__ mixA)
{
    int blk = blockIdx.x;
    int chain = blk >> 5, c = blk & 31;
    int bb = chain >> 3, hh = chain & 7;
    const float* prevC = prevA + (size_t)chain*SS*64;
    const float* bC    = bA    + (size_t)chain*SS*64;
    const float* qlC   = qlA   + (size_t)chain*SS*64;
    const float* pdC   = pdA   + (size_t)chain*SS;
    const float* Pc    = Psnap + (((size_t)chain*NCHUNK + c)*64)*64;

    extern __shared__ float sm[];
    float* ql_s = sm;
    float* pw_s = sm + 4224;
    float* b_s  = sm + 8448;
    float* P_s  = sm + 12672;
    float* sh_pd  = sm + 16896;
    float* sh_cp  = sh_pd + 64;
    float* sh_inv = sh_cp + 64;

    int tid = threadIdx.x;
    int r = tid >> 2, cc = (tid & 3) * 16;
    {
        const float* gq = qlC   + ((size_t)c*64 + r)*64 + cc;
        const float* gp = prevC + ((size_t)c*64 + r)*64 + cc;
        const float* gb = bC    + ((size_t)c*64 + r)*64 + cc;
        const float* gP = Pc    + (size_t)r*64 + cc;
        #pragma unroll
        for (int q = 0; q < 4; q++) {
            float4 v;
            v = *(const float4*)(gq + q*4);
            *(float2*)&ql_s[r*66 + cc + q*4    ] = make_float2(v.x, v.y);
            *(float2*)&ql_s[r*66 + cc + q*4 + 2] = make_float2(v.z, v.w);
            v = *(const float4*)(gp + q*4);
            *(float2*)&pw_s[r*66 + cc + q*4    ] = make_float2(v.x, v.y);
            *(float2*)&pw_s[r*66 + cc + q*4 + 2] = make_float2(v.z, v.w);
            v = *(const float4*)(gb + q*4);
            *(float2*)&b_s[r*66 + cc + q*4    ] = make_float2(v.x, v.y);
            *(float2*)&b_s[r*66 + cc + q*4 + 2] = make_float2(v.z, v.w);
            v = *(const float4*)(gP + q*4);
            *(float2*)&P_s[r*66 + cc + q*4    ] = make_float2(v.x, v.y);
            *(float2*)&P_s[r*66 + cc + q*4 + 2] = make_float2(v.z, v.w);
        }
        if (tid < 64) sh_pd[tid] = pdC[c*64 + tid];
    }
    __syncthreads();
    if (tid == 0) {
        float cp = 1.0f;
        for (int j = 0; j < 64; j++) { cp = fmaxf(cp * sh_pd[j], 1e-35f); sh_cp[j] = cp; }
    }
    __syncthreads();
    if (tid < 64) sh_inv[tid] = 1.0f / sh_cp[tid];

    int t0 = (tid >> 4) * 4, j0 = (tid & 15) * 4;
    ull g2[4][4];
    #pragma unroll
    for (int i = 0; i < 4; i++)
        #pragma unroll
        for (int j = 0; j < 4; j++) g2[i][j] = 0ULL;
    #pragma unroll 8
    for (int kp = 0; kp < 32; kp++) {
        ull aq[4], pj[4];
        #pragma unroll
        for (int i = 0; i < 4; i++) aq[i] = *(const ull*)&ql_s[(t0+i)*66 + 2*kp];
        #pragma unroll
        for (int j = 0; j < 4; j++) pj[j] = *(const ull*)&pw_s[(j0+j)*66 + 2*kp];
        #pragma unroll
        for (int i = 0; i < 4; i++)
            #pragma unroll
            for (int j = 0; j < 4; j++)
                g2[i][j] = fma2(aq[i], pj[j], g2[i][j]);
    }
    float wv[4][4];
    #pragma unroll
    for (int i = 0; i < 4; i++) {
        int tt = t0 + i;
        float cpt = sh_cp[tt];
        #pragma unroll
        for (int j = 0; j < 4; j++) {
            int jj = j0 + j;
            float lo, hi; upk2(g2[i][j], lo, hi);
            float coef = (jj <= tt) ? (1.0f - sh_pd[jj]) * cpt * sh_inv[jj] : 0.0f;
            wv[i][j] = (lo + hi) * coef;
        }
    }
    __syncthreads();
    #pragma unroll
    for (int i = 0; i < 4; i++)
        #pragma unroll
        for (int j = 0; j < 4; j++)
            pw_s[(t0+i)*66 + (j0+j)] = wv[i][j];
    __syncthreads();

    int e0 = j0;
    ull lc2[4][2], st2[4][2];
    #pragma unroll
    for (int i = 0; i < 4; i++) { lc2[i][0]=lc2[i][1]=st2[i][0]=st2[i][1]=0ULL; }
    for (int j = 0; j < 64; j++) {
        ull b20 = *(const ull*)&b_s[j*66 + e0];
        ull b21 = *(const ull*)&b_s[j*66 + e0 + 2];
        ull P20 = *(const ull*)&P_s[j*66 + e0];
        ull P21 = *(const ull*)&P_s[j*66 + e0 + 2];
        #pragma unroll
        for (int i = 0; i < 4; i++) {
            float w = pw_s[(t0+i)*66 + j];
            ull w2 = pk2(w, w);
            lc2[i][0] = fma2(w2, b20, lc2[i][0]);
            lc2[i][1] = fma2(w2, b21, lc2[i][1]);
            float q = ql_s[(t0+i)*66 + j];
            ull q2 = pk2(q, q);
            st2[i][0] = fma2(q2, P20, st2[i][0]);
            st2[i][1] = fma2(q2, P21, st2[i][1]);
        }
    }
    #pragma unroll
    for (int i = 0; i < 4; i++) {
        float cpt = sh_cp[t0 + i];
        ull cp2 = pk2(cpt, cpt);
        ull r0 = fma2(cp2, st2[i][0], lc2[i][0]);
        ull r1 = fma2(cp2, st2[i][1], lc2[i][1]);
        float l0, h0, l1, h1;
        upk2(r0, l0, h0); upk2(r1, l1, h1);
        int tglob = c*64 + t0 + i;
        size_t oo = ((size_t)bb*SS + tglob)*DMODEL + (size_t)hh*64 + e0;
        float4 qr4 = *(const float4*)(qrA + oo);
        float4 ov = make_float4(roundtf(l0*qr4.x), roundtf(h0*qr4.y),
                                roundtf(l1*qr4.z), roundtf(h1*qr4.w));
        *(float4*)(mixA + oo) = ov;
    }
}

// ---------------- host ----------------
extern "C" void kernel_launch(void* const* d_in, const int* in_sizes, int n_in,
                              void* d_out, int out_size)
{
    const float* x    = (const float*)d_in[0];
    const float* ng   = (const float*)d_in[1];
    const float* nb   = (const float*)d_in[2];
    const float* fg   = (const float*)d_in[3];
    const float* fb   = (const float*)d_in[4];
    const float* Wa   = (const float*)d_in[5];
    const float* Wb   = (const float*)d_in[6];
    const float* Wql  = (const float*)d_in[7];
    const float* Wqr  = (const float*)d_in[8];
    const float* Wsd  = (const float*)d_in[9];
    const float* bsd  = (const float*)d_in[10];
    const float* Wpd  = (const float*)d_in[11];
    const float* bpd  = (const float*)d_in[12];
    const float* Wout = (const float*)d_in[13];
    const float* W1   = (const float*)d_in[14];
    const float* b1   = (const float*)d_in[15];
    const float* W2   = (const float*)d_in[16];
    const float* b2   = (const float*)d_in[17];
    float* out = (float*)d_out;

    float *n_, *a_, *b_, *ql_, *qr_, *prev_, *sd_, *pd_, *mix_, *r_, *rn_, *h_, *P_, *wr_;
    cudaGetSymbolAddress((void**)&n_,    g_n);
    cudaGetSymbolAddress((void**)&a_,    g_a);
    cudaGetSymbolAddress((void**)&b_,    g_bp);
    cudaGetSymbolAddress((void**)&ql_,   g_ql);
    cudaGetSymbolAddress((void**)&qr_,   g_qr);
    cudaGetSymbolAddress((void**)&prev_, g_prev);
    cudaGetSymbolAddress((void**)&sd_,   g_sd);
    cudaGetSymbolAddress((void**)&pd_,   g_pd);
    cudaGetSymbolAddress((void**)&mix_,  g_mix);
    cudaGetSymbolAddress((void**)&r_,    g_r);
    cudaGetSymbolAddress((void**)&rn_,   g_rn);
    cudaGetSymbolAddress((void**)&h_,    g_h);
    cudaGetSymbolAddress((void**)&P_,    g_P);
    cudaGetSymbolAddress((void**)&wr_,   g_wr);

    const int p2_smem = (4*4224 + 192) * 4;
    cudaFuncSetAttribute(pair_phase2_kernel,
                         cudaFuncAttributeMaxDynamicSharedMemorySize, p2_smem);
    cudaFuncSetAttribute(proj_mma,
                         cudaFuncAttributeMaxDynamicSharedMemorySize, GM_SMEM);
    cudaFuncSetAttribute(gemm_mma<0,false,true,false>,
                         cudaFuncAttributeMaxDynamicSharedMemorySize, GM_SMEM);
    cudaFuncSetAttribute(gemm_mma<2,true,false,true>,
                         cudaFuncAttributeMaxDynamicSharedMemorySize, GM_SMEM);
    cudaFuncSetAttribute(gemm_mma<0,true,true,false>,
                         cudaFuncAttributeMaxDynamicSharedMemorySize, GM_SMEM);

    // 0) pre-round all weights to tf32-exact values
    round_w_kernel<<<W_TOTAL/256/16, 256>>>(Wa, Wb, Wql, Wqr, Wout, W1, W2, wr_);

    // 1) LN(x) -> rounded n_
    ln_kernel<<<NTOK, 256>>>(x, ng, nb, n_);

    // 2) fused 4-way projection (tanh on all four)
    proj_mma<<<dim3(8, NTOK/GM_MT), 256, GM_SMEM>>>(n_, wr_, a_, b_, ql_, qr_);
    sdpd_kernel<<<NTOK/8, 256>>>(n_, Wsd, bsd, Wpd, bpd, sd_, pd_);

    // 3) scans (chunked)
    state_scan_kernel<<<NCH, 64>>>(a_, sd_, prev_);
    pair_phase1_kernel<<<NCH, 256>>>(prev_, b_, pd_, P_);
    pair_phase2_kernel<<<NCH*NCHUNK, 256, p2_smem>>>(prev_, b_, ql_, pd_, qr_, P_, mix_);

    // 4) r = x + mix @ Wout^T
    dim3 gP512(512/GM_NT, NTOK/GM_MT);
    gemm_mma<0,false,true,false><<<gP512, 256, GM_SMEM>>>(mix_, wr_ + OFF_WOUT, nullptr, x, r_, NTOK, 512, 512);

    // 5) FFN
    ln_kernel<<<NTOK, 256>>>(r_, fg, fb, rn_);
    dim3 gW1(HID/GM_NT, NTOK/GM_MT);
    gemm_mma<2,true,false,true><<<gW1, 256, GM_SMEM>>>(rn_, wr_ + OFF_W1, b1, nullptr, h_, NTOK, HID, 512);
    dim3 gW2(512/GM_NT, NTOK/GM_MT);
    gemm_mma<0,true,true,false><<<gW2, 256, GM_SMEM>>>(h_, wr_ + OFF_W2, b2, r_, out, NTOK, 512, HID);
}

// round 12
// speedup vs baseline: 3.6686x; 1.0182x over previous
#include <cuda_runtime.h>
#include <math.h>
#include <stdint.h>

#define BB 8
#define SS 2048
#define DMODEL 512
#define HH 8
#define NTOK (BB*SS)      /* 16384 */
#define HID 2048
#define NCH (BB*HH)       /* 64 */
#define NCHUNK 32         /* 2048/64 */

typedef unsigned long long ull;

// rounded-weight scratch offsets (floats)
#define OFF_WB   262144
#define OFF_WQL  524288
#define OFF_WQR  786432
#define OFF_WOUT 1048576
#define OFF_W1   1310720
#define OFF_W2   2359296
#define W_TOTAL  3407872

// k-octet permutation: fragment pair (k, k+4) becomes adjacent
__host__ __device__ __forceinline__ int pk8(int k) { return ((k & 3) * 2) | ((k >> 2) & 1); }
__host__ __device__ __forceinline__ int pkf(int d) { return (d & ~7) | pk8(d & 7); }

// ---------------- scratch (device globals: allocation-free rule) ----------------
__device__ float g_n   [NTOK*DMODEL];   // PERM (GEMM-A + sdpd)
__device__ float g_a   [NTOK*DMODEL];   // chain-major, true
__device__ float g_bp  [NTOK*DMODEL];
__device__ float g_ql  [NTOK*DMODEL];
__device__ float g_qr  [NTOK*DMODEL];   // token-major, true
__device__ float g_prev[NTOK*DMODEL];
__device__ float g_sd  [NCH*SS];
__device__ float g_pd  [NCH*SS];
__device__ float g_mix [NTOK*DMODEL];   // PERM (Wout GEMM A)
__device__ float g_r   [NTOK*DMODEL];   // true
__device__ float g_rn  [NTOK*DMODEL];   // PERM (W1 GEMM A)
__device__ float g_h   [NTOK*HID];      // PERM (W2 GEMM A)
__device__ float g_P   [(size_t)NCH*NCHUNK*64*64];
__device__ float g_wr  [W_TOTAL];       // tf32-rounded + PERM weights

// ---------------- f32x2 packed helpers ----------------
__device__ __forceinline__ ull pk2(float a, float b) {
    ull r; asm("mov.b64 %0, {%1, %2};" : "=l"(r) : "f"(a), "f"(b)); return r;
}
__device__ __forceinline__ void upk2(ull v, float& a, float& b) {
    asm("mov.b64 {%0, %1}, %2;" : "=f"(a), "=f"(b) : "l"(v));
}
__device__ __forceinline__ ull fma2(ull a, ull b, ull c) {
    ull d; asm("fma.rn.f32x2 %0, %1, %2, %3;" : "=l"(d) : "l"(a), "l"(b), "l"(c)); return d;
}
__device__ __forceinline__ ull mul2(ull a, ull b) {
    ull d; asm("mul.rn.f32x2 %0, %1, %2;" : "=l"(d) : "l"(a), "l"(b)); return d;
}

// ---------------- mma.sync tf32 + cp.async ----------------
__device__ __forceinline__ uint32_t smem_u32(const void* p) {
    uint32_t a;
    asm("{ .reg .u64 t; cvta.to.shared.u64 t, %1; cvt.u32.u64 %0, t; }" : "=r"(a) : "l"(p));
    return a;
}
__device__ __forceinline__ void mma_tf32(float* c, uint32_t a0, uint32_t a1, uint32_t a2, uint32_t a3,
                                         uint32_t b0, uint32_t b1) {
    asm volatile(
        "mma.sync.aligned.m16n8k8.row.col.f32.tf32.tf32.f32 "
        "{%0,%1,%2,%3}, {%4,%5,%6,%7}, {%8,%9}, {%0,%1,%2,%3};\n"
        : "+f"(c[0]), "+f"(c[1]), "+f"(c[2]), "+f"(c[3])
        : "r"(a0), "r"(a1), "r"(a2), "r"(a3), "r"(b0), "r"(b1));
}
__device__ __forceinline__ uint32_t f2tf(float x) {
    uint32_t r;
    asm("cvt.rna.tf32.f32 %0, %1;" : "=r"(r) : "f"(x));
    return r;
}
__device__ __forceinline__ float roundtf(float x) { return __uint_as_float(f2tf(x)); }
__device__ __forceinline__ void cp16(uint32_t dst, const void* src) {
    asm volatile("cp.async.cg.shared.global [%0], [%1], 16;" :: "r"(dst), "l"(src));
}
__device__ __forceinline__ void cp_commit() { asm volatile("cp.async.commit_group;" ::: "memory"); }
__device__ __forceinline__ void cp_wait1() { asm volatile("cp.async.wait_group 1;" ::: "memory"); }
__device__ __forceinline__ void cp_wait0() { asm volatile("cp.async.wait_group 0;" ::: "memory"); }

// ---------------- weight pre-round + permute pass ----------------
__global__ __launch_bounds__(256) void round_w_kernel(
    const float* __restrict__ Wa, const float* __restrict__ Wb,
    const float* __restrict__ Wql, const float* __restrict__ Wqr,
    const float* __restrict__ Wout, const float* __restrict__ W1,
    const float* __restrict__ W2, float* __restrict__ dst)
{
    int i = blockIdx.x * 256 + threadIdx.x;
    int stride = gridDim.x * 256;
    for (; i < W_TOTAL; i += stride) {
        const float* s; int off, base, Km;
        if      (i < OFF_WB)   { s = Wa;   base = 0;        Km = 512; }
        else if (i < OFF_WQL)  { s = Wb;   base = OFF_WB;   Km = 512; }
        else if (i < OFF_WQR)  { s = Wql;  base = OFF_WQL;  Km = 512; }
        else if (i < OFF_WOUT) { s = Wqr;  base = OFF_WQR;  Km = 512; }
        else if (i < OFF_W1)   { s = Wout; base = OFF_WOUT; Km = 512; }
        else if (i < OFF_W2)   { s = W1;   base = OFF_W1;   Km = 512; }
        else                   { s = W2;   base = OFF_W2;   Km = 2048; }
        off = i - base;
        int row = off / Km, k = off - row * Km;
        dst[base + row * Km + pkf(k)] = roundtf(s[off]);
    }
}

// ================= tensor-pipe GEMM (tf32, pre-rounded PERM operands) =================
// CTA tile 128x256, BK=32, 8 warps (2x4), warp tile 64x64. Double-buffered cp.async.
// Smem stride 40 floats (160B): conflict-free LDS.64 fragment loads.
#define GM_MT 128
#define GM_NT 256
#define GM_KC 32
#define GM_AST 40
#define GM_AFLT (GM_MT*GM_AST)       /* 5120 floats per A buf */
#define GM_BFLT (GM_NT*GM_AST)       /* 10240 floats per B buf */
#define GM_SMEM ((2*GM_AFLT + 2*GM_BFLT)*4)   /* 122880 B */

template<int ACT, bool BIASF, bool RES, bool PERM>
__device__ __forceinline__ void gemm_body(
    const float* __restrict__ A, const float* __restrict__ W,
    const float* __restrict__ bias, const float* __restrict__ resid,
    float* __restrict__ C, int N, int K, int m0, int n0, bool scat,
    float* smf)
{
    float* As = smf;
    float* Bs = smf + 2*GM_AFLT;
    uint32_t sA = smem_u32(As), sB = smem_u32(Bs);

    int tid = threadIdx.x;
    int w = tid >> 5, lane = tid & 31;
    int g = lane >> 2, tig = lane & 3;
    int wr = w >> 2, wc = w & 3;
    int mW = wr * 64, nW = wc * 64;

    float acc[4][8][4];
    #pragma unroll
    for (int i = 0; i < 4; i++)
        #pragma unroll
        for (int j = 0; j < 8; j++)
            #pragma unroll
            for (int r = 0; r < 4; r++) acc[i][j][r] = 0.f;

    const int NC = K / GM_KC;

    auto load_chunk = [&](int c, int buf) {
        const float* Ag = A + (size_t)m0 * K + (size_t)c * GM_KC;
        const float* Wg = W + (size_t)n0 * K + (size_t)c * GM_KC;
        uint32_t ab = sA + (uint32_t)buf * GM_AFLT * 4;
        uint32_t bb = sB + (uint32_t)buf * GM_BFLT * 4;
        #pragma unroll
        for (int p = 0; p < 4; p++) {
            int idx = p * 256 + tid;
            int row = idx >> 3, kc = (idx & 7) * 4;
            cp16(ab + (uint32_t)(row * GM_AST + kc) * 4, Ag + (size_t)row * K + kc);
        }
        #pragma unroll
        for (int p = 0; p < 8; p++) {
            int idx = p * 256 + tid;
            int row = idx >> 3, kc = (idx & 7) * 4;
            cp16(bb + (uint32_t)(row * GM_AST + kc) * 4, Wg + (size_t)row * K + kc);
        }
        cp_commit();
    };

    load_chunk(0, 0);

    for (int c = 0; c < NC; c++) {
        if (c + 1 < NC) { load_chunk(c + 1, (c + 1) & 1); cp_wait1(); }
        else cp_wait0();
        __syncthreads();
        const float* Asf = As + (c & 1) * GM_AFLT;
        const float* Bsf = Bs + (c & 1) * GM_BFLT;

        // software-pipelined LDS.64 fragment loads (operands k-octet-permuted)
        uint2 af2[2][4][2], bf2[2][8];
        #pragma unroll
        for (int i = 0; i < 4; i++) {
            const float* base = Asf + (mW + 16*i + g) * GM_AST + 2*tig;
            af2[0][i][0] = *(const uint2*)(base);
            af2[0][i][1] = *(const uint2*)(base + 8*GM_AST);
        }
        #pragma unroll
        for (int j = 0; j < 8; j++)
            bf2[0][j] = *(const uint2*)(Bsf + (nW + 8*j + g) * GM_AST + 2*tig);

        #pragma unroll
        for (int ks = 0; ks < 4; ks++) {
            int cur = ks & 1;
            if (ks < 3) {
                int kb = (ks + 1) * 8;
                #pragma unroll
                for (int i = 0; i < 4; i++) {
                    const float* base = Asf + (mW + 16*i + g) * GM_AST + kb + 2*tig;
                    af2[cur^1][i][0] = *(const uint2*)(base);
                    af2[cur^1][i][1] = *(const uint2*)(base + 8*GM_AST);
                }
                #pragma unroll
                for (int j = 0; j < 8; j++)
                    bf2[cur^1][j] = *(const uint2*)(Bsf + (nW + 8*j + g) * GM_AST + kb + 2*tig);
            }
            #pragma unroll
            for (int i = 0; i < 4; i++)
                #pragma unroll
                for (int j = 0; j < 8; j++)
                    mma_tf32(acc[i][j],
                             af2[cur][i][0].x, af2[cur][i][1].x,
                             af2[cur][i][0].y, af2[cur][i][1].y,
                             bf2[cur][j].x, bf2[cur][j].y);
        }
        __syncthreads();
    }

    // -------- epilogue --------
    #pragma unroll
    for (int i = 0; i < 4; i++) {
        #pragma unroll
        for (int half = 0; half < 2; half++) {
            int row = m0 + mW + 16*i + g + half*8;
            #pragma unroll
            for (int j = 0; j < 8; j++) {
                int col = n0 + nW + 8*j + 2*tig;
                float v0 = acc[i][j][half*2 + 0];
                float v1 = acc[i][j][half*2 + 1];
                if (BIASF) { v0 += __ldg(bias + col); v1 += __ldg(bias + col + 1); }
                if (ACT == 1) { v0 = tanhf(v0); v1 = tanhf(v1); }
                if (ACT == 2) {
                    v0 = 0.5f * v0 * (1.0f + erff(v0 * 0.70710678118654752f));
                    v1 = 0.5f * v1 * (1.0f + erff(v1 * 0.70710678118654752f));
                }
                if (RES) {
                    float2 rv = *(const float2*)(resid + (size_t)row * N + col);
                    v0 += rv.x; v1 += rv.y;
                }
                if (PERM) {
                    // round + permuted scatter (feeds a downstream GEMM)
                    size_t rb = (size_t)row * N;
                    C[rb + pkf(col)]     = roundtf(v0);
                    C[rb + pkf(col + 1)] = roundtf(v1);
                } else if (scat) {
                    size_t base = ((size_t)((row >> 11) * HH + (col >> 6))) * ((size_t)SS * 64)
                                + (size_t)(row & (SS - 1)) * 64 + (size_t)(col & 63);
                    *(float2*)(C + base) = make_float2(v0, v1);
                } else {
                    *(float2*)(C + (size_t)row * N + col) = make_float2(v0, v1);
                }
            }
        }
    }
}

template<int ACT, bool BIASF, bool RES, bool PERM>
__global__ __launch_bounds__(256, 1) void gemm_mma(
    const float* __restrict__ A, const float* __restrict__ W,
    const float* __restrict__ bias, const float* __restrict__ resid,
    float* __restrict__ C, int M, int N, int K)
{
    extern __shared__ __align__(16) float smf[];
    gemm_body<ACT, BIASF, RES, PERM>(A, W, bias, resid, C, N, K,
                                     blockIdx.y * GM_MT, blockIdx.x * GM_NT, false, smf);
}

// fused 4-way projection: grid.x = 8 (wsel = bx>>1, n-half = bx&1), grid.y = 128
__global__ __launch_bounds__(256, 1) void proj_mma(
    const float* __restrict__ A, const float* __restrict__ Wr,
    float* __restrict__ a_o, float* __restrict__ b_o,
    float* __restrict__ ql_o, float* __restrict__ qr_o)
{
    extern __shared__ __align__(16) float smf[];
    int wsel = blockIdx.x >> 1;
    int n0 = (blockIdx.x & 1) * GM_NT;
    const float* W = Wr + (size_t)wsel * 262144;
    float* C = (wsel == 0) ? a_o : (wsel == 1) ? b_o : (wsel == 2) ? ql_o : qr_o;
    bool scat = (wsel < 3);
    gemm_body<1, false, false, false>(A, W, nullptr, nullptr, C, 512, 512,
                                      blockIdx.y * GM_MT, n0, scat, smf);
}

// ---------------- LayerNorm (tf32-rounded + PERM output) ----------------
__global__ __launch_bounds__(256) void ln_kernel(
    const float* __restrict__ X, const float* __restrict__ G,
    const float* __restrict__ Bt, float* __restrict__ O)
{
    int row = blockIdx.x;
    int tid = threadIdx.x;
    const float* xr = X + (size_t)row*DMODEL;
    float2 v = *(const float2*)(xr + tid*2);
    float s  = v.x + v.y;
    float ss = v.x*v.x + v.y*v.y;
    #pragma unroll
    for (int m = 16; m > 0; m >>= 1) {
        s  += __shfl_xor_sync(0xffffffffu, s,  m);
        ss += __shfl_xor_sync(0xffffffffu, ss, m);
    }
    __shared__ float shs[8], shss[8];
    int w = tid >> 5, l = tid & 31;
    if (l == 0) { shs[w] = s; shss[w] = ss; }
    __syncthreads();
    if (tid == 0) {
        float S_ = 0.f, SS_ = 0.f;
        #pragma unroll
        for (int i = 0; i < 8; i++) { S_ += shs[i]; SS_ += shss[i]; }
        shs[0] = S_; shss[0] = SS_;
    }
    __syncthreads();
    float mean = shs[0] * (1.0f/DMODEL);
    float var  = shss[0] * (1.0f/DMODEL) - mean*mean;
    float inv  = rsqrtf(var + 1e-5f);
    float2 gv = *(const float2*)(G  + tid*2);
    float2 bv = *(const float2*)(Bt + tid*2);
    float o0 = roundtf((v.x - mean)*inv*gv.x + bv.x);
    float o1 = roundtf((v.y - mean)*inv*gv.y + bv.y);
    float* orow = O + (size_t)row*DMODEL;
    orow[pkf(2*tid)]     = o0;
    orow[pkf(2*tid + 1)] = o1;
}

// ---------------- sd/pd gates (n is PERM; permute W identically) ----------------
__global__ __launch_bounds__(256) void sdpd_kernel(
    const float* __restrict__ Nn, const float* __restrict__ Wsd, const float* __restrict__ bsd,
    const float* __restrict__ Wpd, const float* __restrict__ bpd,
    float* __restrict__ sd_o, float* __restrict__ pd_o)
{
    __shared__ float Wsh[16][512];
    __shared__ float nsh[512];
    int tid = threadIdx.x;
    #pragma unroll
    for (int k = 0; k < 32; k++) {
        int idx = tid + 256*k;
        float v = (idx < 4096) ? Wsd[idx] : Wpd[idx - 4096];
        Wsh[idx >> 9][pkf(idx & 511)] = v;   // match permuted n
    }
    int o = tid >> 4, p = tid & 15;
    float bias_v = (o < 8) ? __ldg(bsd + o) : __ldg(bpd + o - 8);
    for (int tk = 0; tk < 8; tk++) {
        int token = blockIdx.x*8 + tk;
        __syncthreads();
        nsh[tid]       = Nn[(size_t)token*512 + tid];
        nsh[tid + 256] = Nn[(size_t)token*512 + tid + 256];
        __syncthreads();
        float s = 0.f;
        #pragma unroll
        for (int i = 0; i < 32; i++) {
            int d = i*16 + p;
            s += nsh[d] * Wsh[o][d];
        }
        s += __shfl_xor_sync(0xffffffffu, s, 8);
        s += __shfl_xor_sync(0xffffffffu, s, 4);
        s += __shfl_xor_sync(0xffffffffu, s, 2);
        s += __shfl_xor_sync(0xffffffffu, s, 1);
        if (p == 0) {
            float z = s + bias_v;
            float sg = 1.0f / (1.0f + expf(-z));
            int b = token >> 11, t = token & (SS-1);
            int h = o & 7;
            size_t oi = ((size_t)(b*8 + h))*SS + t;
            if (o < 8) sd_o[oi] = sg; else pd_o[oi] = sg;
        }
    }
}

// ---------------- state scan ----------------
__global__ __launch_bounds__(64) void state_scan_kernel(
    const float* __restrict__ a, const float* __restrict__ sd, float* __restrict__ prev)
{
    int chain = blockIdx.x, tid = threadIdx.x;
    const float* aP  = a  + (size_t)chain*SS*64;
    const float* sdP = sd + (size_t)chain*SS;
    float* pP        = prev + (size_t)chain*SS*64;
    float st = 0.0f;
    for (int t0 = 0; t0 < SS; t0 += 8) {
        float av[8], sv[8];
        #pragma unroll
        for (int j = 0; j < 8; j++) av[j] = aP[(size_t)(t0+j)*64 + tid];
        #pragma unroll
        for (int j = 0; j < 8; j++) sv[j] = __ldg(sdP + t0 + j);
        #pragma unroll
        for (int j = 0; j < 8; j++) {
            pP[(size_t)(t0+j)*64 + tid] = st;
            st = sv[j]*st + (1.0f - sv[j])*av[j];
        }
    }
}

// ---------------- chunked pair recurrence, phase 1 ----------------
__global__ __launch_bounds__(256) void pair_phase1_kernel(
    const float* __restrict__ prevA, const float* __restrict__ bA,
    const float* __restrict__ pdA, float* __restrict__ Psnap)
{
    int chain = blockIdx.x;
    const float* prevC = prevA + (size_t)chain*SS*64;
    const float* bC    = bA    + (size_t)chain*SS*64;
    const float* pdC   = pdA   + (size_t)chain*SS;
    __shared__ float prev_s[64*66];
    __shared__ float b_s[64*66];
    __shared__ float sh_pd[64], sh_cp[64], sh_u[64];
    int tid = threadIdx.x;
    int d0 = (tid >> 4) * 4, e0 = (tid & 15) * 4;
    int r = tid >> 2, cc = (tid & 3) * 16;

    ull p2[4][2];
    #pragma unroll
    for (int i = 0; i < 4; i++) { p2[i][0] = 0ULL; p2[i][1] = 0ULL; }

    for (int c = 0; c < NCHUNK; c++) {
        __syncthreads();
        {
            const float* gp = prevC + ((size_t)c*64 + r)*64 + cc;
            const float* gb = bC    + ((size_t)c*64 + r)*64 + cc;
            #pragma unroll
            for (int q = 0; q < 4; q++) {
                float4 v = *(const float4*)(gp + q*4);
                *(float2*)&prev_s[r*66 + cc + q*4    ] = make_float2(v.x, v.y);
                *(float2*)&prev_s[r*66 + cc + q*4 + 2] = make_float2(v.z, v.w);
                float4 u = *(const float4*)(gb + q*4);
                *(float2*)&b_s[r*66 + cc + q*4    ] = make_float2(u.x, u.y);
                *(float2*)&b_s[r*66 + cc + q*4 + 2] = make_float2(u.z, u.w);
            }
            if (tid < 64) sh_pd[tid] = pdC[c*64 + tid];
        }
        __syncthreads();
        if (tid == 0) {
            float cp = 1.0f;
            for (int j = 0; j < 64; j++) { cp = fmaxf(cp * sh_pd[j], 1e-35f); sh_cp[j] = cp; }
        }
        __syncthreads();
        if (tid < 64) sh_u[tid] = (1.0f - sh_pd[tid]) * (sh_cp[63] / sh_cp[tid]);
        float* Pc = Psnap + (((size_t)chain*NCHUNK + c)*64)*64;
        #pragma unroll
        for (int i = 0; i < 4; i++) {
            float l0, h0, l1, h1;
            upk2(p2[i][0], l0, h0); upk2(p2[i][1], l1, h1);
            float4 v = make_float4(l0, h0, l1, h1);
            *(float4*)(Pc + (size_t)(d0+i)*64 + e0) = v;
        }
        __syncthreads();
        float cpE = sh_cp[63];
        ull cpE2 = pk2(cpE, cpE);
        #pragma unroll
        for (int i = 0; i < 4; i++) {
            p2[i][0] = mul2(p2[i][0], cpE2);
            p2[i][1] = mul2(p2[i][1], cpE2);
        }
        for (int j = 0; j < 64; j++) {
            float uj = sh_u[j];
            ull b20 = *(const ull*)&b_s[j*66 + e0];
            ull b21 = *(const ull*)&b_s[j*66 + e0 + 2];
            #pragma unroll
            for (int i = 0; i < 4; i++) {
                float s = uj * prev_s[j*66 + d0 + i];
                ull s2 = pk2(s, s);
                p2[i][0] = fma2(s2, b20, p2[i][0]);
                p2[i][1] = fma2(s2, b21, p2[i][1]);
            }
        }
    }
}

// ---------------- chunked pair, phase 2 (mix: rounded + PERM store) ----------------
__global__ __launch_bounds__(256) void pair_phase2_kernel(
    const float* __restrict__ prevA, const float* __restrict__ bA,
    const float* __restrict__ qlA,   const float* __restrict__ pdA,
    const float* __restrict__ qrA,   const float* __restrict__ Psnap,
    float* __restrict__ mixA)
{
    int blk = blockIdx.x;
    int chain = blk >> 5, c = blk & 31;
    int bb = chain >> 3, hh = chain & 7;
    const float* prevC = prevA + (size_t)chain*SS*64;
    const float* bC    = bA    + (size_t)chain*SS*64;
    const float* qlC   = qlA   + (size_t)chain*SS*64;
    const float* pdC   = pdA   + (size_t)chain*SS;
    const float* Pc    = Psnap + (((size_t)chain*NCHUNK + c)*64)*64;

    extern __shared__ float sm[];
    float* ql_s = sm;
    float* pw_s = sm + 4224;
    float* b_s  = sm + 8448;
    float* P_s  = sm + 12672;
    float* sh_pd  = sm + 16896;
    float* sh_cp  = sh_pd + 64;
    float* sh_inv = sh_cp + 64;

    int tid = threadIdx.x;
    int r = tid >> 2, cc = (tid & 3) * 16;
    {
        const float* gq = qlC   + ((size_t)c*64 + r)*64 + cc;
        const float* gp = prevC + ((size_t)c*64 + r)*64 + cc;
        const float* gb = bC    + ((size_t)c*64 + r)*64 + cc;
        const float* gP = Pc    + (size_t)r*64 + cc;
        #pragma unroll
        for (int q = 0; q < 4; q++) {
            float4 v;
            v = *(const float4*)(gq + q*4);
            *(float2*)&ql_s[r*66 + cc + q*4    ] = make_float2(v.x, v.y);
            *(float2*)&ql_s[r*66 + cc + q*4 + 2] = make_float2(v.z, v.w);
            v = *(const float4*)(gp + q*4);
            *(float2*)&pw_s[r*66 + cc + q*4    ] = make_float2(v.x, v.y);
            *(float2*)&pw_s[r*66 + cc + q*4 + 2] = make_float2(v.z, v.w);
            v = *(const float4*)(gb + q*4);
            *(float2*)&b_s[r*66 + cc + q*4    ] = make_float2(v.x, v.y);
            *(float2*)&b_s[r*66 + cc + q*4 + 2] = make_float2(v.z, v.w);
            v = *(const float4*)(gP + q*4);
            *(float2*)&P_s[r*66 + cc + q*4    ] = make_float2(v.x, v.y);
            *(float2*)&P_s[r*66 + cc + q*4 + 2] = make_float2(v.z, v.w);
        }
        if (tid < 64) sh_pd[tid] = pdC[c*64 + tid];
    }
    __syncthreads();
    if (tid == 0) {
        float cp = 1.0f;
        for (int j = 0; j < 64; j++) { cp = fmaxf(cp * sh_pd[j], 1e-35f); sh_cp[j] = cp; }
    }
    __syncthreads();
    if (tid < 64) sh_inv[tid] = 1.0f / sh_cp[tid];

    int t0 = (tid >> 4) * 4, j0 = (tid & 15) * 4;
    ull g2[4][4];
    #pragma unroll
    for (int i = 0; i < 4; i++)
        #pragma unroll
        for (int j = 0; j < 4; j++) g2[i][j] = 0ULL;
    #pragma unroll 8
    for (int kp = 0; kp < 32; kp++) {
        ull aq[4], pj[4];
        #pragma unroll
        for (int i = 0; i < 4; i++) aq[i] = *(const ull*)&ql_s[(t0+i)*66 + 2*kp];
        #pragma unroll
        for (int j = 0; j < 4; j++) pj[j] = *(const ull*)&pw_s[(j0+j)*66 + 2*kp];
        #pragma unroll
        for (int i = 0; i < 4; i++)
            #pragma unroll
            for (int j = 0; j < 4; j++)
                g2[i][j] = fma2(aq[i], pj[j], g2[i][j]);
    }
    float wv[4][4];
    #pragma unroll
    for (int i = 0; i < 4; i++) {
        int tt = t0 + i;
        float cpt = sh_cp[tt];
        #pragma unroll
        for (int j = 0; j < 4; j++) {
            int jj = j0 + j;
            float lo, hi; upk2(g2[i][j], lo, hi);
            float coef = (jj <= tt) ? (1.0f - sh_pd[jj]) * cpt * sh_inv[jj] : 0.0f;
            wv[i][j] = (lo + hi) * coef;
        }
    }
    __syncthreads();
    #pragma unroll
    for (int i = 0; i < 4; i++)
        #pragma unroll
        for (int j = 0; j < 4; j++)
            pw_s[(t0+i)*66 + (j0+j)] = wv[i][j];
    __syncthreads();

    int e0 = j0;
    ull lc2[4][2], st2[4][2];
    #pragma unroll
    for (int i = 0; i < 4; i++) { lc2[i][0]=lc2[i][1]=st2[i][0]=st2[i][1]=0ULL; }
    for (int j = 0; j < 64; j++) {
        ull b20 = *(const ull*)&b_s[j*66 + e0];
        ull b21 = *(const ull*)&b_s[j*66 + e0 + 2];
        ull P20 = *(const ull*)&P_s[j*66 + e0];
        ull P21 = *(const ull*)&P_s[j*66 + e0 + 2];
        #pragma unroll
        for (int i = 0; i < 4; i++) {
            float w = pw_s[(t0+i)*66 + j];
            ull w2 = pk2(w, w);
            lc2[i][0] = fma2(w2, b20, lc2[i][0]);
            lc2[i][1] = fma2(w2, b21, lc2[i][1]);
            float q = ql_s[(t0+i)*66 + j];
            ull q2 = pk2(q, q);
            st2[i][0] = fma2(q2, P20, st2[i][0]);
            st2[i][1] = fma2(q2, P21, st2[i][1]);
        }
    }
    #pragma unroll
    for (int i = 0; i < 4; i++) {
        float cpt = sh_cp[t0 + i];
        ull cp2 = pk2(cpt, cpt);
        ull r0 = fma2(cp2, st2[i][0], lc2[i][0]);
        ull r1 = fma2(cp2, st2[i][1], lc2[i][1]);
        float l0, h0, l1, h1;
        upk2(r0, l0, h0); upk2(r1, l1, h1);
        int tglob = c*64 + t0 + i;
        size_t rb = ((size_t)bb*SS + tglob)*DMODEL;
        int colb = hh*64 + e0;
        float4 qr4 = *(const float4*)(qrA + rb + colb);
        float ov[4] = { roundtf(l0*qr4.x), roundtf(h0*qr4.y),
                        roundtf(l1*qr4.z), roundtf(h1*qr4.w) };
        #pragma unroll
        for (int u = 0; u < 4; u++)
            mixA[rb + pkf(colb + u)] = ov[u];   // permuted: feeds Wout GEMM
    }
}

// ---------------- host ----------------
extern "C" void kernel_launch(void* const* d_in, const int* in_sizes, int n_in,
                              void* d_out, int out_size)
{
    const float* x    = (const float*)d_in[0];
    const float* ng   = (const float*)d_in[1];
    const float* nb   = (const float*)d_in[2];
    const float* fg   = (const float*)d_in[3];
    const float* fb   = (const float*)d_in[4];
    const float* Wa   = (const float*)d_in[5];
    const float* Wb   = (const float*)d_in[6];
    const float* Wql  = (const float*)d_in[7];
    const float* Wqr  = (const float*)d_in[8];
    const float* Wsd  = (const float*)d_in[9];
    const float* bsd  = (const float*)d_in[10];
    const float* Wpd  = (const float*)d_in[11];
    const float* bpd  = (const float*)d_in[12];
    const float* Wout = (const float*)d_in[13];
    const float* W1   = (const float*)d_in[14];
    const float* b1   = (const float*)d_in[15];
    const float* W2   = (const float*)d_in[16];
    const float* b2   = (const float*)d_in[17];
    float* out = (float*)d_out;

    float *n_, *a_, *b_, *ql_, *qr_, *prev_, *sd_, *pd_, *mix_, *r_, *rn_, *h_, *P_, *wr_;
    cudaGetSymbolAddress((void**)&n_,    g_n);
    cudaGetSymbolAddress((void**)&a_,    g_a);
    cudaGetSymbolAddress((void**)&b_,    g_bp);
    cudaGetSymbolAddress((void**)&ql_,   g_ql);
    cudaGetSymbolAddress((void**)&qr_,   g_qr);
    cudaGetSymbolAddress((void**)&prev_, g_prev);
    cudaGetSymbolAddress((void**)&sd_,   g_sd);
    cudaGetSymbolAddress((void**)&pd_,   g_pd);
    cudaGetSymbolAddress((void**)&mix_,  g_mix);
    cudaGetSymbolAddress((void**)&r_,    g_r);
    cudaGetSymbolAddress((void**)&rn_,   g_rn);
    cudaGetSymbolAddress((void**)&h_,    g_h);
    cudaGetSymbolAddress((void**)&P_,    g_P);
    cudaGetSymbolAddress((void**)&wr_,   g_wr);

    const int p2_smem = (4*4224 + 192) * 4;
    cudaFuncSetAttribute(pair_phase2_kernel,
                         cudaFuncAttributeMaxDynamicSharedMemorySize, p2_smem);
    cudaFuncSetAttribute(proj_mma,
                         cudaFuncAttributeMaxDynamicSharedMemorySize, GM_SMEM);
    cudaFuncSetAttribute(gemm_mma<0,false,true,false>,
                         cudaFuncAttributeMaxDynamicSharedMemorySize, GM_SMEM);
    cudaFuncSetAttribute(gemm_mma<2,true,false,true>,
                         cudaFuncAttributeMaxDynamicSharedMemorySize, GM_SMEM);
    cudaFuncSetAttribute(gemm_mma<0,true,true,false>,
                         cudaFuncAttributeMaxDynamicSharedMemorySize, GM_SMEM);

    // 0) pre-round + permute all weights
    round_w_kernel<<<832, 256>>>(Wa, Wb, Wql, Wqr, Wout, W1, W2, wr_);

    // 1) LN(x) -> rounded+perm n_
    ln_kernel<<<NTOK, 256>>>(x, ng, nb, n_);

    // 2) fused 4-way projection (tanh) + gates
    proj_mma<<<dim3(8, NTOK/GM_MT), 256, GM_SMEM>>>(n_, wr_, a_, b_, ql_, qr_);
    sdpd_kernel<<<NTOK/8, 256>>>(n_, Wsd, bsd, Wpd, bpd, sd_, pd_);

    // 3) scans (chunked)
    state_scan_kernel<<<NCH, 64>>>(a_, sd_, prev_);
    pair_phase1_kernel<<<NCH, 256>>>(prev_, b_, pd_, P_);
    pair_phase2_kernel<<<NCH*NCHUNK, 256, p2_smem>>>(prev_, b_, ql_, pd_, qr_, P_, mix_);

    // 4) r = x + mix @ Wout^T  (r_ true layout)
    dim3 gP512(512/GM_NT, NTOK/GM_MT);
    gemm_mma<0,false,true,false><<<gP512, 256, GM_SMEM>>>(mix_, wr_ + OFF_WOUT, nullptr, x, r_, NTOK, 512, 512);

    // 5) FFN
    ln_kernel<<<NTOK, 256>>>(r_, fg, fb, rn_);
    dim3 gW1(HID/GM_NT, NTOK/GM_MT);
    gemm_mma<2,true,false,true><<<gW1, 256, GM_SMEM>>>(rn_, wr_ + OFF_W1, b1, nullptr, h_, NTOK, HID, 512);
    dim3 gW2(512/GM_NT, NTOK/GM_MT);
    gemm_mma<0,true,true,false><<<gW2, 256, GM_SMEM>>>(h_, wr_ + OFF_W2, b2, r_, out, NTOK, 512, HID);
}